// round 2
// baseline (speedup 1.0000x reference)
#include <cuda_runtime.h>
#include <math.h>

#define BB   4
#define SS   1024
#define DD   1024
#define HH   16
#define DK_  64
#define DV_  128
#define LL   3
#define FFN_ 4096
#define MM   (BB*SS)   // 4096 tokens

// ------------------------------------------------------------------
// Scratch buffers (static device allocations; no cudaMalloc allowed)
// ------------------------------------------------------------------
__device__ float g_h  [MM*DD];       // residual stream
__device__ float g_x  [MM*DD];       // LN output
__device__ float g_q  [MM*DD];
__device__ float g_k  [MM*DD];
__device__ float g_v  [MM*2*DD];
__device__ float g_g  [MM*2*DD];     // gate pre-activation
__device__ float g_ao [MM*2*DD];     // gated attention output
__device__ float g_y  [MM*DD];       // GEMM output before residual add
__device__ float g_ffn[MM*FFN_];     // FFN intermediate
__device__ float g_sin[SS*32];
__device__ float g_cos[SS*32];

// ------------------------------------------------------------------
// Helpers
// ------------------------------------------------------------------
__device__ __forceinline__ float gelu_tanh(float v) {
    const float c = 0.7978845608028654f;   // sqrt(2/pi)
    return 0.5f * v * (1.0f + tanhf(c * (v + 0.044715f * v * v * v)));
}

__device__ __forceinline__ float blockReduceSum(float val, float* sh) {
    #pragma unroll
    for (int off = 16; off > 0; off >>= 1)
        val += __shfl_xor_sync(0xffffffffu, val, off);
    int w = threadIdx.x >> 5, l = threadIdx.x & 31;
    __syncthreads();               // protect sh reuse across calls
    if (l == 0) sh[w] = val;
    __syncthreads();
    float r = (threadIdx.x < (blockDim.x >> 5)) ? sh[threadIdx.x] : 0.0f;
    if (w == 0) {
        #pragma unroll
        for (int off = 16; off > 0; off >>= 1)
            r += __shfl_xor_sync(0xffffffffu, r, off);
        if (l == 0) sh[0] = r;
    }
    __syncthreads();
    return sh[0];
}

// ------------------------------------------------------------------
// sin/cos rotary tables (double precision)
// ------------------------------------------------------------------
__global__ void sincos_kernel(float* __restrict__ sint, float* __restrict__ cost) {
    int idx = blockIdx.x * blockDim.x + threadIdx.x;
    if (idx >= SS * 32) return;
    int i = idx & 31;
    int s = idx >> 5;
    double ang = pow(10000.0, -(double)i / 31.0);
    double a = (double)s * ang;
    sint[idx] = (float)sin(a);
    cost[idx] = (float)cos(a);
}

// ------------------------------------------------------------------
// Embedding with right-shift: h[b,s,:] = emb[shifted_token] * sqrt(D)
// ------------------------------------------------------------------
__global__ void embed_kernel(const int* __restrict__ tokens,
                             const float* __restrict__ emb,
                             float* __restrict__ h) {
    int idx = blockIdx.x * blockDim.x + threadIdx.x;
    if (idx >= MM * DD) return;
    int d  = idx & (DD - 1);
    int bs = idx / DD;
    int s  = bs & (SS - 1);
    int b  = bs / SS;
    int tok = (s == 0) ? 0 : tokens[b * SS + s - 1];
    h[idx] = emb[tok * DD + d] * 32.0f;   // sqrt(1024) = 32 exact
}

// ------------------------------------------------------------------
// LayerNorm (two-pass, eps 1e-5), one block per token row
// ------------------------------------------------------------------
__global__ __launch_bounds__(256)
void ln_kernel(const float* __restrict__ x, const float* __restrict__ sc,
               const float* __restrict__ bi, float* __restrict__ y) {
    __shared__ float sh[32];
    int row = blockIdx.x;
    int tid = threadIdx.x;
    const float* xr = x + (size_t)row * DD;
    float v[4];
    float sum = 0.0f;
    #pragma unroll
    for (int j = 0; j < 4; j++) { v[j] = xr[tid + j * 256]; sum += v[j]; }
    sum = blockReduceSum(sum, sh);
    float mean = sum * (1.0f / 1024.0f);
    float vs = 0.0f;
    #pragma unroll
    for (int j = 0; j < 4; j++) { float d = v[j] - mean; vs += d * d; }
    vs = blockReduceSum(vs, sh);
    float invstd = rsqrtf(vs * (1.0f / 1024.0f) + 1e-5f);
    float* yr = y + (size_t)row * DD;
    #pragma unroll
    for (int j = 0; j < 4; j++) {
        int c = tid + j * 256;
        yr[c] = (v[j] - mean) * invstd * sc[c] + bi[c];
    }
}

// ------------------------------------------------------------------
// Tiled SGEMM: C[M,N] = A[M,K] @ B[K,N] (+bias, +gelu)
// 64x64 tile, BK=16, 256 threads, 4x4 per thread
// epi: 0 = none, 1 = +bias, 2 = gelu(+bias)
// ------------------------------------------------------------------
__global__ __launch_bounds__(256)
void gemm_kernel(const float* __restrict__ A, const float* __restrict__ B,
                 const float* __restrict__ bias, float* __restrict__ C,
                 int M, int N, int K, int epi) {
    __shared__ float As[16 * 68];   // [k][m], padded
    __shared__ float Bs[16 * 64];   // [k][n]
    int tid = threadIdx.x;
    int tx = tid & 15, ty = tid >> 4;
    int m0 = blockIdx.y * 64, n0 = blockIdx.x * 64;
    int am = tid >> 2, ak = (tid & 3) * 4;
    int bk = tid >> 4, bn = (tid & 15) * 4;
    const float* Ap = A + (size_t)(m0 + am) * K + ak;
    const float* Bp = B + (size_t)bk * N + n0 + bn;
    float acc[4][4] = {};
    for (int k0 = 0; k0 < K; k0 += 16) {
        float4 a4 = *(const float4*)(Ap + k0);
        float4 b4 = *(const float4*)(Bp + (size_t)k0 * N);
        __syncthreads();
        As[(ak + 0) * 68 + am] = a4.x;
        As[(ak + 1) * 68 + am] = a4.y;
        As[(ak + 2) * 68 + am] = a4.z;
        As[(ak + 3) * 68 + am] = a4.w;
        *(float4*)&Bs[bk * 64 + bn] = b4;
        __syncthreads();
        #pragma unroll
        for (int kk = 0; kk < 16; kk++) {
            float4 av = *(const float4*)&As[kk * 68 + ty * 4];
            float4 bv = *(const float4*)&Bs[kk * 64 + tx * 4];
            float a[4] = {av.x, av.y, av.z, av.w};
            float bb[4] = {bv.x, bv.y, bv.z, bv.w};
            #pragma unroll
            for (int i = 0; i < 4; i++)
                #pragma unroll
                for (int j = 0; j < 4; j++)
                    acc[i][j] += a[i] * bb[j];
        }
    }
    int row = m0 + ty * 4, col = n0 + tx * 4;
    #pragma unroll
    for (int i = 0; i < 4; i++)
        #pragma unroll
        for (int j = 0; j < 4; j++) {
            float vres = acc[i][j];
            if (epi >= 1) vres += bias[col + j];
            if (epi == 2) vres = gelu_tanh(vres);
            C[(size_t)(row + i) * N + col + j] = vres;
        }
}

// ------------------------------------------------------------------
// Rotary (interleaved pairs), k also scaled by DK^-0.5 = 0.125 (exact)
// ------------------------------------------------------------------
__global__ void rotary_kernel(float* __restrict__ q, float* __restrict__ k,
                              const float* __restrict__ sint,
                              const float* __restrict__ cost) {
    int idx = blockIdx.x * blockDim.x + threadIdx.x;   // BB*SS*HH*32
    if (idx >= BB * SS * HH * 32) return;
    int i  = idx & 31;
    int t  = idx >> 5;
    int h  = t & 15;
    int bs = t >> 4;
    int s  = bs & (SS - 1);
    float sn = sint[s * 32 + i];
    float cs = cost[s * 32 + i];
    size_t base = (size_t)bs * DD + h * 64 + 2 * i;
    float q0 = q[base], q1 = q[base + 1];
    q[base]     = q0 * cs - q1 * sn;
    q[base + 1] = q1 * cs + q0 * sn;
    float k0 = k[base], k1 = k[base + 1];
    k[base]     = (k0 * cs - k1 * sn) * 0.125f;
    k[base + 1] = (k1 * cs + k0 * sn) * 0.125f;
}

// ------------------------------------------------------------------
// Fused retention attention:
//   s[n,m]  = (q.k) * gamma^(n-m) * c(h,n)       (causal)
//   denom   = max(1, sum_m |s|)
//   o[n,:]  = (s @ v) / denom
//   o      /= sqrt(mean(o^2) + 1e-6)             (per-head RMS)
//   out     = silu(gate) * o
// One block = (b, h, 64 query rows). 256 threads.
// absum accumulation: per-tile partials in red[256], tree-reduced by 16
// threads per row (no shared atomics).
// ------------------------------------------------------------------
#define ATTN_SHMEM ((64*68*2 + 64*128 + 64*65 + 64 + 64 + 256) * 4)

__global__ __launch_bounds__(256)
void attn_kernel(const float* __restrict__ q, const float* __restrict__ k,
                 const float* __restrict__ v, const float* __restrict__ g,
                 float* __restrict__ outp) {
    extern __shared__ float sh[];
    float* QsT   = sh;                 // [64 k][68]  (k-major, padded)
    float* KsT   = QsT + 64 * 68;      // [64 k][68]
    float* Vs    = KsT + 64 * 68;      // [64 m][128]
    float* St    = Vs + 64 * 128;      // [64 r][65]
    float* absum = St + 64 * 65;       // [64]
    float* crow  = absum + 64;         // [64]
    float* red   = crow + 64;          // [256] scratch

    int tid = threadIdx.x;
    int nt = blockIdx.x, h = blockIdx.y, b = blockIdx.z;
    int n0 = nt * 64;
    int tx = tid & 15, ty = tid >> 4;

    double gamma_d = 1.0 - exp2((double)(-5 - h));
    float lg2g = (float)log2(gamma_d);

    // Load Q tile (transposed to k-major)
    #pragma unroll
    for (int qq = 0; qq < 4; qq++) {
        int p = tid + qq * 256;
        int r = p >> 4;
        int kq = (p & 15) * 4;
        float4 t4 = *(const float4*)&q[((size_t)(b * SS + n0 + r)) * DD + h * 64 + kq];
        QsT[(kq + 0) * 68 + r] = t4.x;
        QsT[(kq + 1) * 68 + r] = t4.y;
        QsT[(kq + 2) * 68 + r] = t4.z;
        QsT[(kq + 3) * 68 + r] = t4.w;
    }
    if (tid < 64) {
        absum[tid] = 0.0f;
        int n = n0 + tid;
        double ssum = (1.0 - pow(gamma_d, (double)(n + 1))) / (1.0 - gamma_d);
        crow[tid] = (float)(1.0 / sqrt(ssum));
    }
    float oa[32];
    #pragma unroll
    for (int i = 0; i < 32; i++) oa[i] = 0.0f;
    int ro = tid >> 2, cg = tid & 3;

    for (int mt = 0; mt <= nt; mt++) {
        int m0 = mt * 64;
        __syncthreads();   // protect shared tiles from previous iteration's reads
        // Load K tile (k-major)
        #pragma unroll
        for (int qq = 0; qq < 4; qq++) {
            int p = tid + qq * 256;
            int m = p >> 4;
            int kq = (p & 15) * 4;
            float4 t4 = *(const float4*)&k[((size_t)(b * SS + m0 + m)) * DD + h * 64 + kq];
            KsT[(kq + 0) * 68 + m] = t4.x;
            KsT[(kq + 1) * 68 + m] = t4.y;
            KsT[(kq + 2) * 68 + m] = t4.z;
            KsT[(kq + 3) * 68 + m] = t4.w;
        }
        // Load V tile (row-major)
        #pragma unroll
        for (int qq = 0; qq < 8; qq++) {
            int p = tid + qq * 256;
            int m = p >> 5;
            int c4 = (p & 31) * 4;
            *(float4*)&Vs[m * 128 + c4] =
                *(const float4*)&v[((size_t)(b * SS + m0 + m)) * (2 * DD) + h * 128 + c4];
        }
        __syncthreads();

        // Score stage: 64x64x64 GEMM, thread = 4x4
        float scv[4][4] = {};
        #pragma unroll 4
        for (int kk = 0; kk < 64; kk++) {
            float4 av = *(const float4*)&QsT[kk * 68 + ty * 4];
            float4 bv = *(const float4*)&KsT[kk * 68 + tx * 4];
            float a[4] = {av.x, av.y, av.z, av.w};
            float bb[4] = {bv.x, bv.y, bv.z, bv.w};
            #pragma unroll
            for (int i = 0; i < 4; i++)
                #pragma unroll
                for (int j = 0; j < 4; j++)
                    scv[i][j] += a[i] * bb[j];
        }
        // Decay + mask + row-norm factor; write St; per-thread |.| partials
        float aps[4];
        #pragma unroll
        for (int i = 0; i < 4; i++) {
            int r = ty * 4 + i;
            int n = n0 + r;
            float cc = crow[r];
            float part = 0.0f;
            #pragma unroll
            for (int j = 0; j < 4; j++) {
                int m = m0 + tx * 4 + j;
                float t = 0.0f;
                if (m <= n) t = scv[i][j] * exp2f((float)(n - m) * lg2g) * cc;
                St[r * 65 + tx * 4 + j] = t;
                part += fabsf(t);
            }
            aps[i] = part;
        }
        // Reduce the 16 tx-partials per row via warp shuffles.
        // Threads with the same ty (row group) are tid = ty*16 + tx, so
        // tx-neighbors are lane-adjacent: shuffle works within the warp.
        #pragma unroll
        for (int i = 0; i < 4; i++) {
            float p4 = aps[i];
            #pragma unroll
            for (int off = 8; off > 0; off >>= 1)
                p4 += __shfl_xor_sync(0xffffffffu, p4, off);
            if (tx == 0) absum[ty * 4 + i] += p4;   // one writer per row
        }
        __syncthreads();

        // o accumulation: thread = (row ro, column group cg: c = jj*16+cg*4+q)
        for (int m = 0; m < 64; m++) {
            float sv = St[ro * 65 + m];
            const float* vr = &Vs[m * 128];
            #pragma unroll
            for (int jj = 0; jj < 8; jj++) {
                float4 vv = *(const float4*)&vr[jj * 16 + cg * 4];
                oa[jj * 4 + 0] += sv * vv.x;
                oa[jj * 4 + 1] += sv * vv.y;
                oa[jj * 4 + 2] += sv * vv.z;
                oa[jj * 4 + 3] += sv * vv.w;
            }
        }
    }
    __syncthreads();

    // Finalize: L1 clip, RMS over DV, SiLU gate, write out
    float inv = 1.0f / fmaxf(1.0f, absum[ro]);
    float ssq = 0.0f;
    #pragma unroll
    for (int t = 0; t < 32; t++) { oa[t] *= inv; ssq += oa[t] * oa[t]; }
    red[ro * 4 + cg] = ssq;
    __syncthreads();
    float sum = red[ro * 4 + 0] + red[ro * 4 + 1] + red[ro * 4 + 2] + red[ro * 4 + 3];
    float scale = rsqrtf(sum * (1.0f / 128.0f) + 1e-6f);
    int n = n0 + ro;
    size_t gb = ((size_t)(b * SS + n)) * (2 * DD) + h * 128;
    #pragma unroll
    for (int jj = 0; jj < 8; jj++)
        #pragma unroll
        for (int qi = 0; qi < 4; qi++) {
            int c = jj * 16 + cg * 4 + qi;
            float gv = g[gb + c];
            float sl = gv / (1.0f + expf(-gv));
            outp[gb + c] = sl * (oa[jj * 4 + qi] * scale);
        }
}

// ------------------------------------------------------------------
// Residual add: a += b (float4)
// ------------------------------------------------------------------
__global__ void add_kernel(float* __restrict__ a, const float* __restrict__ bsrc, int n4) {
    int i = blockIdx.x * blockDim.x + threadIdx.x;
    if (i < n4) {
        float4 x = ((float4*)a)[i];
        float4 yv = ((const float4*)bsrc)[i];
        x.x += yv.x; x.y += yv.y; x.z += yv.z; x.w += yv.w;
        ((float4*)a)[i] = x;
    }
}

// ------------------------------------------------------------------
// Final logits + log_softmax (V=2), one warp per token
// ------------------------------------------------------------------
__global__ void logits_kernel(const float* __restrict__ x,
                              const float* __restrict__ Wout,
                              float* __restrict__ outp) {
    int gt = blockIdx.x * blockDim.x + threadIdx.x;
    int warp = gt >> 5, lane = gt & 31;
    if (warp >= MM) return;
    const float* xr = x + (size_t)warp * DD;
    float a0 = 0.0f, a1 = 0.0f;
    for (int kk = lane; kk < DD; kk += 32) {
        float xv = xr[kk];
        a0 += xv * Wout[kk * 2 + 0];
        a1 += xv * Wout[kk * 2 + 1];
    }
    #pragma unroll
    for (int off = 16; off > 0; off >>= 1) {
        a0 += __shfl_xor_sync(0xffffffffu, a0, off);
        a1 += __shfl_xor_sync(0xffffffffu, a1, off);
    }
    if (lane == 0) {
        float mx = fmaxf(a0, a1);
        float lse = mx + logf(expf(a0 - mx) + expf(a1 - mx));
        outp[warp * 2 + 0] = a0 - lse;
        outp[warp * 2 + 1] = a1 - lse;
    }
}

// ------------------------------------------------------------------
// Orchestration
// ------------------------------------------------------------------
extern "C" void kernel_launch(void* const* d_in, const int* in_sizes, int n_in,
                              void* d_out, int out_size) {
    const int*   tokens = (const int*)  d_in[0];
    const float* emb    = (const float*)d_in[1];
    const float* Wq     = (const float*)d_in[2];
    const float* Wk     = (const float*)d_in[3];
    const float* Wv     = (const float*)d_in[4];
    const float* Wg     = (const float*)d_in[5];
    const float* Wo     = (const float*)d_in[6];
    const float* ln1_s  = (const float*)d_in[7];
    const float* ln1_b  = (const float*)d_in[8];
    const float* ln2_s  = (const float*)d_in[9];
    const float* ln2_b  = (const float*)d_in[10];
    const float* W1     = (const float*)d_in[11];
    const float* b1     = (const float*)d_in[12];
    const float* W2     = (const float*)d_in[13];
    const float* b2     = (const float*)d_in[14];
    const float* lnf_s  = (const float*)d_in[15];
    const float* lnf_b  = (const float*)d_in[16];
    const float* Wout   = (const float*)d_in[17];

    float *h, *x, *q, *k, *v, *g, *ao, *y, *ffn, *sint, *cost;
    cudaGetSymbolAddress((void**)&h,    g_h);
    cudaGetSymbolAddress((void**)&x,    g_x);
    cudaGetSymbolAddress((void**)&q,    g_q);
    cudaGetSymbolAddress((void**)&k,    g_k);
    cudaGetSymbolAddress((void**)&v,    g_v);
    cudaGetSymbolAddress((void**)&g,    g_g);
    cudaGetSymbolAddress((void**)&ao,   g_ao);
    cudaGetSymbolAddress((void**)&y,    g_y);
    cudaGetSymbolAddress((void**)&ffn,  g_ffn);
    cudaGetSymbolAddress((void**)&sint, g_sin);
    cudaGetSymbolAddress((void**)&cost, g_cos);

    cudaFuncSetAttribute(attn_kernel, cudaFuncAttributeMaxDynamicSharedMemorySize,
                         ATTN_SHMEM);

    sincos_kernel<<<(SS * 32 + 255) / 256, 256>>>(sint, cost);
    embed_kernel<<<(MM * DD + 255) / 256, 256>>>(tokens, emb, h);

    const int n4 = MM * DD / 4;
    for (int l = 0; l < LL; l++) {
        const float* Wq_l = Wq + (size_t)l * DD * DD;
        const float* Wk_l = Wk + (size_t)l * DD * DD;
        const float* Wv_l = Wv + (size_t)l * DD * 2 * DD;
        const float* Wg_l = Wg + (size_t)l * DD * 2 * DD;
        const float* Wo_l = Wo + (size_t)l * 2 * DD * DD;
        const float* W1_l = W1 + (size_t)l * DD * FFN_;
        const float* W2_l = W2 + (size_t)l * FFN_ * DD;
        const float* b1_l = b1 + (size_t)l * FFN_;
        const float* b2_l = b2 + (size_t)l * DD;

        // --- MSR block ---
        ln_kernel<<<MM, 256>>>(h, ln1_s + l * DD, ln1_b + l * DD, x);
        gemm_kernel<<<dim3(DD / 64, MM / 64), 256>>>(x, Wq_l, nullptr, q, MM, DD, DD, 0);
        gemm_kernel<<<dim3(DD / 64, MM / 64), 256>>>(x, Wk_l, nullptr, k, MM, DD, DD, 0);
        gemm_kernel<<<dim3(2 * DD / 64, MM / 64), 256>>>(x, Wv_l, nullptr, v, MM, 2 * DD, DD, 0);
        gemm_kernel<<<dim3(2 * DD / 64, MM / 64), 256>>>(x, Wg_l, nullptr, g, MM, 2 * DD, DD, 0);
        rotary_kernel<<<(BB * SS * HH * 32 + 255) / 256, 256>>>(q, k, sint, cost);
        attn_kernel<<<dim3(SS / 64, HH, BB), 256, ATTN_SHMEM>>>(q, k, v, g, ao);
        gemm_kernel<<<dim3(DD / 64, MM / 64), 256>>>(ao, Wo_l, nullptr, y, MM, DD, 2 * DD, 0);
        add_kernel<<<(n4 + 255) / 256, 256>>>(h, y, n4);

        // --- FFN block ---
        ln_kernel<<<MM, 256>>>(h, ln2_s + l * DD, ln2_b + l * DD, x);
        gemm_kernel<<<dim3(FFN_ / 64, MM / 64), 256>>>(x, W1_l, b1_l, ffn, MM, FFN_, DD, 2);
        gemm_kernel<<<dim3(DD / 64, MM / 64), 256>>>(ffn, W2_l, b2_l, y, MM, DD, FFN_, 1);
        add_kernel<<<(n4 + 255) / 256, 256>>>(h, y, n4);
    }

    ln_kernel<<<MM, 256>>>(h, lnf_s, lnf_b, x);
    logits_kernel<<<MM * 32 / 256, 256>>>(x, Wout, (float*)d_out);
}

// round 4
// speedup vs baseline: 2.1010x; 2.1010x over previous
#include <cuda_runtime.h>
#include <math.h>
#include <stdint.h>

#define BB   4
#define SS   1024
#define DD   1024
#define HH   16
#define DK_  64
#define DV_  128
#define LL   3
#define FFN_ 4096
#define MM   (BB*SS)   // 4096 tokens

// ------------------------------------------------------------------
// Scratch buffers (static device allocations; no cudaMalloc allowed)
// ------------------------------------------------------------------
__device__ float g_h  [MM*DD];       // residual stream
__device__ float g_x  [MM*DD];       // LN output
__device__ float g_q  [MM*DD];
__device__ float g_k  [MM*DD];
__device__ float g_v  [MM*2*DD];
__device__ float g_g  [MM*2*DD];     // gate pre-activation
__device__ float g_ao [MM*2*DD];     // gated attention output
__device__ float g_y  [MM*DD];       // GEMM output before residual add
__device__ float g_ffn[MM*FFN_];     // FFN intermediate
__device__ float g_sin[SS*32];
__device__ float g_cos[SS*32];

// ------------------------------------------------------------------
// Helpers
// ------------------------------------------------------------------
__device__ __forceinline__ float gelu_tanh(float v) {
    const float c = 0.7978845608028654f;   // sqrt(2/pi)
    return 0.5f * v * (1.0f + tanhf(c * (v + 0.044715f * v * v * v)));
}

__device__ __forceinline__ uint32_t f2tf(float x) {
    uint32_t r;
    asm("cvt.rna.tf32.f32 %0, %1;" : "=r"(r) : "f"(x));
    return r;
}

__device__ __forceinline__ float blockReduceSum(float val, float* sh) {
    #pragma unroll
    for (int off = 16; off > 0; off >>= 1)
        val += __shfl_xor_sync(0xffffffffu, val, off);
    int w = threadIdx.x >> 5, l = threadIdx.x & 31;
    __syncthreads();
    if (l == 0) sh[w] = val;
    __syncthreads();
    float r = (threadIdx.x < (blockDim.x >> 5)) ? sh[threadIdx.x] : 0.0f;
    if (w == 0) {
        #pragma unroll
        for (int off = 16; off > 0; off >>= 1)
            r += __shfl_xor_sync(0xffffffffu, r, off);
        if (l == 0) sh[0] = r;
    }
    __syncthreads();
    return sh[0];
}

// ------------------------------------------------------------------
// sin/cos rotary tables (double precision)
// ------------------------------------------------------------------
__global__ void sincos_kernel(float* __restrict__ sint, float* __restrict__ cost) {
    int idx = blockIdx.x * blockDim.x + threadIdx.x;
    if (idx >= SS * 32) return;
    int i = idx & 31;
    int s = idx >> 5;
    double ang = pow(10000.0, -(double)i / 31.0);
    double a = (double)s * ang;
    sint[idx] = (float)sin(a);
    cost[idx] = (float)cos(a);
}

// ------------------------------------------------------------------
// Embedding with right-shift
// ------------------------------------------------------------------
__global__ void embed_kernel(const int* __restrict__ tokens,
                             const float* __restrict__ emb,
                             float* __restrict__ h) {
    int idx = blockIdx.x * blockDim.x + threadIdx.x;
    if (idx >= MM * DD) return;
    int d  = idx & (DD - 1);
    int bs = idx / DD;
    int s  = bs & (SS - 1);
    int b  = bs / SS;
    int tok = (s == 0) ? 0 : tokens[b * SS + s - 1];
    h[idx] = emb[tok * DD + d] * 32.0f;
}

// ------------------------------------------------------------------
// LayerNorm (two-pass, eps 1e-5), one block per token row
// ------------------------------------------------------------------
__global__ __launch_bounds__(256)
void ln_kernel(const float* __restrict__ x, const float* __restrict__ sc,
               const float* __restrict__ bi, float* __restrict__ y) {
    __shared__ float sh[32];
    int row = blockIdx.x;
    int tid = threadIdx.x;
    const float* xr = x + (size_t)row * DD;
    float v[4];
    float sum = 0.0f;
    #pragma unroll
    for (int j = 0; j < 4; j++) { v[j] = xr[tid + j * 256]; sum += v[j]; }
    sum = blockReduceSum(sum, sh);
    float mean = sum * (1.0f / 1024.0f);
    float vs = 0.0f;
    #pragma unroll
    for (int j = 0; j < 4; j++) { float d = v[j] - mean; vs += d * d; }
    vs = blockReduceSum(vs, sh);
    float invstd = rsqrtf(vs * (1.0f / 1024.0f) + 1e-5f);
    float* yr = y + (size_t)row * DD;
    #pragma unroll
    for (int j = 0; j < 4; j++) {
        int c = tid + j * 256;
        yr[c] = (v[j] - mean) * invstd * sc[c] + bi[c];
    }
}

// ------------------------------------------------------------------
// TF32 tensor-core GEMM: C[M,N] = A[M,K] @ B[K,N] (+bias, +gelu)
// Block tile 128x128, BK=32, 256 threads (8 warps, 4x2), warp tile 32x64.
// mma.sync.aligned.m16n8k8 tf32, fp32 accumulate. Double-buffered SMEM.
// epi: 0 = none, 1 = +bias, 2 = gelu(+bias)
// ------------------------------------------------------------------
#define ASZ (128 * 36)     // A smem buffer, stride 36 words (conflict-free)
#define BSZ (32 * 136)     // B smem buffer, stride 136 words (conflict-free)
#define GEMM_SMEM ((2 * ASZ + 2 * BSZ) * 4)

__device__ __forceinline__ void mma_tf32(float* c, const uint32_t* a, const uint32_t* b) {
    asm volatile(
        "mma.sync.aligned.m16n8k8.row.col.f32.tf32.tf32.f32 "
        "{%0,%1,%2,%3}, {%4,%5,%6,%7}, {%8,%9}, {%0,%1,%2,%3};\n"
        : "+f"(c[0]), "+f"(c[1]), "+f"(c[2]), "+f"(c[3])
        : "r"(a[0]), "r"(a[1]), "r"(a[2]), "r"(a[3]), "r"(b[0]), "r"(b[1]));
}

__global__ __launch_bounds__(256)
void gemm_tf32_kernel(const float* __restrict__ A, const float* __restrict__ B,
                      const float* __restrict__ bias, float* __restrict__ C,
                      int M, int N, int K, int epi) {
    extern __shared__ uint32_t smu[];
    uint32_t* As = smu;              // [2][ASZ]
    uint32_t* Bs = smu + 2 * ASZ;    // [2][BSZ]

    int tid  = threadIdx.x;
    int wid  = tid >> 5, lane = tid & 31;
    int g    = lane >> 2, t = lane & 3;
    int wm   = wid & 3;              // warp row   (0..3) -> m offset wm*32
    int wn   = wid >> 2;             // warp col   (0..1) -> n offset wn*64
    int m0   = blockIdx.y * 128, n0 = blockIdx.x * 128;

    float acc[2][8][4];
    #pragma unroll
    for (int i = 0; i < 2; i++)
        #pragma unroll
        for (int j = 0; j < 8; j++)
            #pragma unroll
            for (int r = 0; r < 4; r++) acc[i][j][r] = 0.0f;

    int nk = K >> 5;   // K/32

    // ---- prologue: tile 0 into buffer 0
    #pragma unroll
    for (int q = 0; q < 4; q++) {
        int lin = tid + q * 256;
        int r = lin >> 3, c4 = (lin & 7) * 4;
        float4 v4 = *(const float4*)&A[(size_t)(m0 + r) * K + c4];
        uint32_t* dst = &As[r * 36 + c4];
        *(uint4*)dst = make_uint4(f2tf(v4.x), f2tf(v4.y), f2tf(v4.z), f2tf(v4.w));
    }
    #pragma unroll
    for (int q = 0; q < 4; q++) {
        int lin = tid + q * 256;
        int r = lin >> 5, c4 = (lin & 31) * 4;
        float4 v4 = *(const float4*)&B[(size_t)r * N + n0 + c4];
        uint32_t* dst = &Bs[r * 136 + c4];
        *(uint4*)dst = make_uint4(f2tf(v4.x), f2tf(v4.y), f2tf(v4.z), f2tf(v4.w));
    }
    __syncthreads();

    for (int kt = 0; kt < nk; kt++) {
        int buf = kt & 1;
        const uint32_t* Ab = As + buf * ASZ;
        const uint32_t* Bb = Bs + buf * BSZ;

        // prefetch next tile into registers (overlaps with compute)
        float4 pa[4], pb[4];
        bool more = (kt + 1 < nk);
        if (more) {
            int kb = (kt + 1) << 5;
            #pragma unroll
            for (int q = 0; q < 4; q++) {
                int lin = tid + q * 256;
                int r = lin >> 3, c4 = (lin & 7) * 4;
                pa[q] = *(const float4*)&A[(size_t)(m0 + r) * K + kb + c4];
            }
            #pragma unroll
            for (int q = 0; q < 4; q++) {
                int lin = tid + q * 256;
                int r = lin >> 5, c4 = (lin & 31) * 4;
                pb[q] = *(const float4*)&B[(size_t)(kb + r) * N + n0 + c4];
            }
        }

        // compute 4 k-steps of 8
        #pragma unroll
        for (int ks = 0; ks < 4; ks++) {
            int kk = ks * 8;
            uint32_t a[2][4], b[8][2];
            #pragma unroll
            for (int i = 0; i < 2; i++) {
                int rb = wm * 32 + i * 16 + g;
                a[i][0] = Ab[rb * 36 + kk + t];
                a[i][1] = Ab[(rb + 8) * 36 + kk + t];
                a[i][2] = Ab[rb * 36 + kk + t + 4];
                a[i][3] = Ab[(rb + 8) * 36 + kk + t + 4];
            }
            #pragma unroll
            for (int j = 0; j < 8; j++) {
                int cb = wn * 64 + j * 8 + g;
                b[j][0] = Bb[(kk + t) * 136 + cb];
                b[j][1] = Bb[(kk + t + 4) * 136 + cb];
            }
            #pragma unroll
            for (int i = 0; i < 2; i++)
                #pragma unroll
                for (int j = 0; j < 8; j++)
                    mma_tf32(acc[i][j], a[i], b[j]);
        }

        if (more) {
            int nb = buf ^ 1;
            uint32_t* Aw = As + nb * ASZ;
            uint32_t* Bw = Bs + nb * BSZ;
            #pragma unroll
            for (int q = 0; q < 4; q++) {
                int lin = tid + q * 256;
                int r = lin >> 3, c4 = (lin & 7) * 4;
                *(uint4*)&Aw[r * 36 + c4] =
                    make_uint4(f2tf(pa[q].x), f2tf(pa[q].y), f2tf(pa[q].z), f2tf(pa[q].w));
            }
            #pragma unroll
            for (int q = 0; q < 4; q++) {
                int lin = tid + q * 256;
                int r = lin >> 5, c4 = (lin & 31) * 4;
                *(uint4*)&Bw[r * 136 + c4] =
                    make_uint4(f2tf(pb[q].x), f2tf(pb[q].y), f2tf(pb[q].z), f2tf(pb[q].w));
            }
            __syncthreads();
        }
    }

    // ---- epilogue
    #pragma unroll
    for (int i = 0; i < 2; i++) {
        int row0 = m0 + wm * 32 + i * 16 + g;
        #pragma unroll
        for (int j = 0; j < 8; j++) {
            int col = n0 + wn * 64 + j * 8 + 2 * t;
            float b0v = 0.0f, b1v = 0.0f;
            if (epi >= 1) { b0v = bias[col]; b1v = bias[col + 1]; }
            float v00 = acc[i][j][0] + b0v, v01 = acc[i][j][1] + b1v;
            float v10 = acc[i][j][2] + b0v, v11 = acc[i][j][3] + b1v;
            if (epi == 2) {
                v00 = gelu_tanh(v00); v01 = gelu_tanh(v01);
                v10 = gelu_tanh(v10); v11 = gelu_tanh(v11);
            }
            float2 lo = make_float2(v00, v01);
            float2 hi = make_float2(v10, v11);
            *(float2*)&C[(size_t)row0 * N + col] = lo;
            *(float2*)&C[(size_t)(row0 + 8) * N + col] = hi;
        }
    }
}

// ------------------------------------------------------------------
// Rotary (interleaved pairs), k also scaled by DK^-0.5 = 0.125
// ------------------------------------------------------------------
__global__ void rotary_kernel(float* __restrict__ q, float* __restrict__ k,
                              const float* __restrict__ sint,
                              const float* __restrict__ cost) {
    int idx = blockIdx.x * blockDim.x + threadIdx.x;
    if (idx >= BB * SS * HH * 32) return;
    int i  = idx & 31;
    int t  = idx >> 5;
    int h  = t & 15;
    int bs = t >> 4;
    int s  = bs & (SS - 1);
    float sn = sint[s * 32 + i];
    float cs = cost[s * 32 + i];
    size_t base = (size_t)bs * DD + h * 64 + 2 * i;
    float q0 = q[base], q1 = q[base + 1];
    q[base]     = q0 * cs - q1 * sn;
    q[base + 1] = q1 * cs + q0 * sn;
    float k0 = k[base], k1 = k[base + 1];
    k[base]     = (k0 * cs - k1 * sn) * 0.125f;
    k[base + 1] = (k1 * cs + k0 * sn) * 0.125f;
}

// ------------------------------------------------------------------
// Fused retention attention
// ------------------------------------------------------------------
#define ATTN_SHMEM ((64*68*2 + 64*128 + 64*65 + 64 + 64 + 256) * 4)

__global__ __launch_bounds__(256)
void attn_kernel(const float* __restrict__ q, const float* __restrict__ k,
                 const float* __restrict__ v, const float* __restrict__ g,
                 float* __restrict__ outp) {
    extern __shared__ float sh[];
    float* QsT   = sh;
    float* KsT   = QsT + 64 * 68;
    float* Vs    = KsT + 64 * 68;
    float* St    = Vs + 64 * 128;
    float* absum = St + 64 * 65;
    float* crow  = absum + 64;
    float* red   = crow + 64;

    int tid = threadIdx.x;
    int nt = blockIdx.x, h = blockIdx.y, b = blockIdx.z;
    int n0 = nt * 64;
    int tx = tid & 15, ty = tid >> 4;

    double gamma_d = 1.0 - exp2((double)(-5 - h));
    float lg2g = (float)log2(gamma_d);

    #pragma unroll
    for (int qq = 0; qq < 4; qq++) {
        int p = tid + qq * 256;
        int r = p >> 4;
        int kq = (p & 15) * 4;
        float4 t4 = *(const float4*)&q[((size_t)(b * SS + n0 + r)) * DD + h * 64 + kq];
        QsT[(kq + 0) * 68 + r] = t4.x;
        QsT[(kq + 1) * 68 + r] = t4.y;
        QsT[(kq + 2) * 68 + r] = t4.z;
        QsT[(kq + 3) * 68 + r] = t4.w;
    }
    if (tid < 64) {
        absum[tid] = 0.0f;
        int n = n0 + tid;
        double ssum = (1.0 - pow(gamma_d, (double)(n + 1))) / (1.0 - gamma_d);
        crow[tid] = (float)(1.0 / sqrt(ssum));
    }
    float oa[32];
    #pragma unroll
    for (int i = 0; i < 32; i++) oa[i] = 0.0f;
    int ro = tid >> 2, cg = tid & 3;

    for (int mt = 0; mt <= nt; mt++) {
        int m0 = mt * 64;
        __syncthreads();
        #pragma unroll
        for (int qq = 0; qq < 4; qq++) {
            int p = tid + qq * 256;
            int m = p >> 4;
            int kq = (p & 15) * 4;
            float4 t4 = *(const float4*)&k[((size_t)(b * SS + m0 + m)) * DD + h * 64 + kq];
            KsT[(kq + 0) * 68 + m] = t4.x;
            KsT[(kq + 1) * 68 + m] = t4.y;
            KsT[(kq + 2) * 68 + m] = t4.z;
            KsT[(kq + 3) * 68 + m] = t4.w;
        }
        #pragma unroll
        for (int qq = 0; qq < 8; qq++) {
            int p = tid + qq * 256;
            int m = p >> 5;
            int c4 = (p & 31) * 4;
            *(float4*)&Vs[m * 128 + c4] =
                *(const float4*)&v[((size_t)(b * SS + m0 + m)) * (2 * DD) + h * 128 + c4];
        }
        __syncthreads();

        float scv[4][4] = {};
        #pragma unroll 4
        for (int kk = 0; kk < 64; kk++) {
            float4 av = *(const float4*)&QsT[kk * 68 + ty * 4];
            float4 bv = *(const float4*)&KsT[kk * 68 + tx * 4];
            float a[4] = {av.x, av.y, av.z, av.w};
            float bb[4] = {bv.x, bv.y, bv.z, bv.w};
            #pragma unroll
            for (int i = 0; i < 4; i++)
                #pragma unroll
                for (int j = 0; j < 4; j++)
                    scv[i][j] += a[i] * bb[j];
        }
        float aps[4];
        #pragma unroll
        for (int i = 0; i < 4; i++) {
            int r = ty * 4 + i;
            int n = n0 + r;
            float cc = crow[r];
            float part = 0.0f;
            #pragma unroll
            for (int j = 0; j < 4; j++) {
                int m = m0 + tx * 4 + j;
                float t = 0.0f;
                if (m <= n) t = scv[i][j] * exp2f((float)(n - m) * lg2g) * cc;
                St[r * 65 + tx * 4 + j] = t;
                part += fabsf(t);
            }
            aps[i] = part;
        }
        #pragma unroll
        for (int i = 0; i < 4; i++) {
            float p4 = aps[i];
            #pragma unroll
            for (int off = 8; off > 0; off >>= 1)
                p4 += __shfl_xor_sync(0xffffffffu, p4, off);
            if (tx == 0) absum[ty * 4 + i] += p4;
        }
        __syncthreads();

        for (int m = 0; m < 64; m++) {
            float sv = St[ro * 65 + m];
            const float* vr = &Vs[m * 128];
            #pragma unroll
            for (int jj = 0; jj < 8; jj++) {
                float4 vv = *(const float4*)&vr[jj * 16 + cg * 4];
                oa[jj * 4 + 0] += sv * vv.x;
                oa[jj * 4 + 1] += sv * vv.y;
                oa[jj * 4 + 2] += sv * vv.z;
                oa[jj * 4 + 3] += sv * vv.w;
            }
        }
    }
    __syncthreads();

    float inv = 1.0f / fmaxf(1.0f, absum[ro]);
    float ssq = 0.0f;
    #pragma unroll
    for (int t = 0; t < 32; t++) { oa[t] *= inv; ssq += oa[t] * oa[t]; }
    red[ro * 4 + cg] = ssq;
    __syncthreads();
    float sum = red[ro * 4 + 0] + red[ro * 4 + 1] + red[ro * 4 + 2] + red[ro * 4 + 3];
    float scale = rsqrtf(sum * (1.0f / 128.0f) + 1e-6f);
    int n = n0 + ro;
    size_t gb = ((size_t)(b * SS + n)) * (2 * DD) + h * 128;
    #pragma unroll
    for (int jj = 0; jj < 8; jj++)
        #pragma unroll
        for (int qi = 0; qi < 4; qi++) {
            int c = jj * 16 + cg * 4 + qi;
            float gv = g[gb + c];
            float sl = gv / (1.0f + expf(-gv));
            outp[gb + c] = sl * (oa[jj * 4 + qi] * scale);
        }
}

// ------------------------------------------------------------------
// Residual add
// ------------------------------------------------------------------
__global__ void add_kernel(float* __restrict__ a, const float* __restrict__ bsrc, int n4) {
    int i = blockIdx.x * blockDim.x + threadIdx.x;
    if (i < n4) {
        float4 x = ((float4*)a)[i];
        float4 yv = ((const float4*)bsrc)[i];
        x.x += yv.x; x.y += yv.y; x.z += yv.z; x.w += yv.w;
        ((float4*)a)[i] = x;
    }
}

// ------------------------------------------------------------------
// Final logits + log_softmax (V=2), one warp per token
// ------------------------------------------------------------------
__global__ void logits_kernel(const float* __restrict__ x,
                              const float* __restrict__ Wout,
                              float* __restrict__ outp) {
    int gt = blockIdx.x * blockDim.x + threadIdx.x;
    int warp = gt >> 5, lane = gt & 31;
    if (warp >= MM) return;
    const float* xr = x + (size_t)warp * DD;
    float a0 = 0.0f, a1 = 0.0f;
    for (int kk = lane; kk < DD; kk += 32) {
        float xv = xr[kk];
        a0 += xv * Wout[kk * 2 + 0];
        a1 += xv * Wout[kk * 2 + 1];
    }
    #pragma unroll
    for (int off = 16; off > 0; off >>= 1) {
        a0 += __shfl_xor_sync(0xffffffffu, a0, off);
        a1 += __shfl_xor_sync(0xffffffffu, a1, off);
    }
    if (lane == 0) {
        float mx = fmaxf(a0, a1);
        float lse = mx + logf(expf(a0 - mx) + expf(a1 - mx));
        outp[warp * 2 + 0] = a0 - lse;
        outp[warp * 2 + 1] = a1 - lse;
    }
}

// ------------------------------------------------------------------
// Orchestration
// ------------------------------------------------------------------
extern "C" void kernel_launch(void* const* d_in, const int* in_sizes, int n_in,
                              void* d_out, int out_size) {
    const int*   tokens = (const int*)  d_in[0];
    const float* emb    = (const float*)d_in[1];
    const float* Wq     = (const float*)d_in[2];
    const float* Wk     = (const float*)d_in[3];
    const float* Wv     = (const float*)d_in[4];
    const float* Wg     = (const float*)d_in[5];
    const float* Wo     = (const float*)d_in[6];
    const float* ln1_s  = (const float*)d_in[7];
    const float* ln1_b  = (const float*)d_in[8];
    const float* ln2_s  = (const float*)d_in[9];
    const float* ln2_b  = (const float*)d_in[10];
    const float* W1     = (const float*)d_in[11];
    const float* b1     = (const float*)d_in[12];
    const float* W2     = (const float*)d_in[13];
    const float* b2     = (const float*)d_in[14];
    const float* lnf_s  = (const float*)d_in[15];
    const float* lnf_b  = (const float*)d_in[16];
    const float* Wout   = (const float*)d_in[17];

    float *h, *x, *q, *k, *v, *g, *ao, *y, *ffn, *sint, *cost;
    cudaGetSymbolAddress((void**)&h,    g_h);
    cudaGetSymbolAddress((void**)&x,    g_x);
    cudaGetSymbolAddress((void**)&q,    g_q);
    cudaGetSymbolAddress((void**)&k,    g_k);
    cudaGetSymbolAddress((void**)&v,    g_v);
    cudaGetSymbolAddress((void**)&g,    g_g);
    cudaGetSymbolAddress((void**)&ao,   g_ao);
    cudaGetSymbolAddress((void**)&y,    g_y);
    cudaGetSymbolAddress((void**)&ffn,  g_ffn);
    cudaGetSymbolAddress((void**)&sint, g_sin);
    cudaGetSymbolAddress((void**)&cost, g_cos);

    cudaFuncSetAttribute(attn_kernel, cudaFuncAttributeMaxDynamicSharedMemorySize,
                         ATTN_SHMEM);
    cudaFuncSetAttribute(gemm_tf32_kernel, cudaFuncAttributeMaxDynamicSharedMemorySize,
                         GEMM_SMEM);

    sincos_kernel<<<(SS * 32 + 255) / 256, 256>>>(sint, cost);
    embed_kernel<<<(MM * DD + 255) / 256, 256>>>(tokens, emb, h);

    const int n4 = MM * DD / 4;
    for (int l = 0; l < LL; l++) {
        const float* Wq_l = Wq + (size_t)l * DD * DD;
        const float* Wk_l = Wk + (size_t)l * DD * DD;
        const float* Wv_l = Wv + (size_t)l * DD * 2 * DD;
        const float* Wg_l = Wg + (size_t)l * DD * 2 * DD;
        const float* Wo_l = Wo + (size_t)l * 2 * DD * DD;
        const float* W1_l = W1 + (size_t)l * DD * FFN_;
        const float* W2_l = W2 + (size_t)l * FFN_ * DD;
        const float* b1_l = b1 + (size_t)l * FFN_;
        const float* b2_l = b2 + (size_t)l * DD;

        // --- MSR block ---
        ln_kernel<<<MM, 256>>>(h, ln1_s + l * DD, ln1_b + l * DD, x);
        gemm_tf32_kernel<<<dim3(DD / 128, MM / 128), 256, GEMM_SMEM>>>(
            x, Wq_l, nullptr, q, MM, DD, DD, 0);
        gemm_tf32_kernel<<<dim3(DD / 128, MM / 128), 256, GEMM_SMEM>>>(
            x, Wk_l, nullptr, k, MM, DD, DD, 0);
        gemm_tf32_kernel<<<dim3(2 * DD / 128, MM / 128), 256, GEMM_SMEM>>>(
            x, Wv_l, nullptr, v, MM, 2 * DD, DD, 0);
        gemm_tf32_kernel<<<dim3(2 * DD / 128, MM / 128), 256, GEMM_SMEM>>>(
            x, Wg_l, nullptr, g, MM, 2 * DD, DD, 0);
        rotary_kernel<<<(BB * SS * HH * 32 + 255) / 256, 256>>>(q, k, sint, cost);
        attn_kernel<<<dim3(SS / 64, HH, BB), 256, ATTN_SHMEM>>>(q, k, v, g, ao);
        gemm_tf32_kernel<<<dim3(DD / 128, MM / 128), 256, GEMM_SMEM>>>(
            ao, Wo_l, nullptr, y, MM, DD, 2 * DD, 0);
        add_kernel<<<(n4 + 255) / 256, 256>>>(h, y, n4);

        // --- FFN block ---
        ln_kernel<<<MM, 256>>>(h, ln2_s + l * DD, ln2_b + l * DD, x);
        gemm_tf32_kernel<<<dim3(FFN_ / 128, MM / 128), 256, GEMM_SMEM>>>(
            x, W1_l, b1_l, ffn, MM, FFN_, DD, 2);
        gemm_tf32_kernel<<<dim3(DD / 128, MM / 128), 256, GEMM_SMEM>>>(
            ffn, W2_l, b2_l, y, MM, DD, FFN_, 1);
        add_kernel<<<(n4 + 255) / 256, 256>>>(h, y, n4);
    }

    ln_kernel<<<MM, 256>>>(h, lnf_s, lnf_b, x);
    logits_kernel<<<MM * 32 / 256, 256>>>(x, Wout, (float*)d_out);
}

// round 9
// speedup vs baseline: 2.1543x; 1.0254x over previous
#include <cuda_runtime.h>
#include <math.h>
#include <stdint.h>

#define BB   4
#define SS   1024
#define DD   1024
#define HH   16
#define DK_  64
#define DV_  128
#define LL   3
#define FFN_ 4096
#define MM   (BB*SS)   // 4096 tokens

// ------------------------------------------------------------------
// Scratch buffers (static device allocations; no cudaMalloc allowed)
// ------------------------------------------------------------------
__device__ float g_h  [MM*DD];       // residual stream
__device__ float g_x  [MM*DD];       // LN output
__device__ float g_q  [MM*DD];
__device__ float g_k  [MM*DD];
__device__ float g_v  [MM*2*DD];
__device__ float g_g  [MM*2*DD];     // gate pre-activation
__device__ float g_ao [MM*2*DD];     // gated attention output
__device__ float g_ffn[MM*FFN_];     // FFN intermediate
__device__ float g_sin[SS*32];
__device__ float g_cos[SS*32];

// ------------------------------------------------------------------
// Helpers
// ------------------------------------------------------------------
__device__ __forceinline__ float gelu_tanh(float v) {
    const float c = 0.7978845608028654f;   // sqrt(2/pi)
    return 0.5f * v * (1.0f + tanhf(c * (v + 0.044715f * v * v * v)));
}

// round-to-nearest tf32 conversion on a raw fp32 bit pattern
__device__ __forceinline__ uint32_t rtf(uint32_t bits) {
    uint32_t r;
    asm("cvt.rna.tf32.f32 %0, %1;" : "=r"(r) : "r"(bits));
    return r;
}

__device__ __forceinline__ void cp16(void* smem_dst, const void* gsrc) {
    uint32_t a = (uint32_t)__cvta_generic_to_shared(smem_dst);
    asm volatile("cp.async.cg.shared.global [%0], [%1], 16;\n" :: "r"(a), "l"(gsrc));
}

__device__ __forceinline__ float blockReduceSum(float val, float* sh) {
    #pragma unroll
    for (int off = 16; off > 0; off >>= 1)
        val += __shfl_xor_sync(0xffffffffu, val, off);
    int w = threadIdx.x >> 5, l = threadIdx.x & 31;
    __syncthreads();
    if (l == 0) sh[w] = val;
    __syncthreads();
    float r = (threadIdx.x < (blockDim.x >> 5)) ? sh[threadIdx.x] : 0.0f;
    if (w == 0) {
        #pragma unroll
        for (int off = 16; off > 0; off >>= 1)
            r += __shfl_xor_sync(0xffffffffu, r, off);
        if (l == 0) sh[0] = r;
    }
    __syncthreads();
    return sh[0];
}

// ------------------------------------------------------------------
// sin/cos rotary tables (double precision)
// ------------------------------------------------------------------
__global__ void sincos_kernel(float* __restrict__ sint, float* __restrict__ cost) {
    int idx = blockIdx.x * blockDim.x + threadIdx.x;
    if (idx >= SS * 32) return;
    int i = idx & 31;
    int s = idx >> 5;
    double ang = pow(10000.0, -(double)i / 31.0);
    double a = (double)s * ang;
    sint[idx] = (float)sin(a);
    cost[idx] = (float)cos(a);
}

// ------------------------------------------------------------------
// Embedding with right-shift
// ------------------------------------------------------------------
__global__ void embed_kernel(const int* __restrict__ tokens,
                             const float* __restrict__ emb,
                             float* __restrict__ h) {
    int idx = blockIdx.x * blockDim.x + threadIdx.x;
    if (idx >= MM * DD) return;
    int d  = idx & (DD - 1);
    int bs = idx / DD;
    int s  = bs & (SS - 1);
    int b  = bs / SS;
    int tok = (s == 0) ? 0 : tokens[b * SS + s - 1];
    h[idx] = emb[tok * DD + d] * 32.0f;
}

// ------------------------------------------------------------------
// LayerNorm (two-pass, eps 1e-5), one block per token row
// ------------------------------------------------------------------
__global__ __launch_bounds__(256)
void ln_kernel(const float* __restrict__ x, const float* __restrict__ sc,
               const float* __restrict__ bi, float* __restrict__ y) {
    __shared__ float sh[32];
    int row = blockIdx.x;
    int tid = threadIdx.x;
    const float* xr = x + (size_t)row * DD;
    float v[4];
    float sum = 0.0f;
    #pragma unroll
    for (int j = 0; j < 4; j++) { v[j] = xr[tid + j * 256]; sum += v[j]; }
    sum = blockReduceSum(sum, sh);
    float mean = sum * (1.0f / 1024.0f);
    float vs = 0.0f;
    #pragma unroll
    for (int j = 0; j < 4; j++) { float d = v[j] - mean; vs += d * d; }
    vs = blockReduceSum(vs, sh);
    float invstd = rsqrtf(vs * (1.0f / 1024.0f) + 1e-5f);
    float* yr = y + (size_t)row * DD;
    #pragma unroll
    for (int j = 0; j < 4; j++) {
        int c = tid + j * 256;
        yr[c] = (v[j] - mean) * invstd * sc[c] + bi[c];
    }
}

// ------------------------------------------------------------------
// TF32 tensor-core GEMM: C[M,N] = A[M,K] @ B[K,N]
// Block tile 128x128, BK=32, 256 threads (8 warps, 4x2), warp tile 32x64.
// cp.async 3-stage pipeline; SMEM holds raw fp32; cvt.rna.tf32 applied to
// fragments in registers before mma.sync (round-to-nearest, unbiased).
// epi bitmask: 1 = +bias, 2 = gelu, 4 = accumulate into C (C += result)
// ------------------------------------------------------------------
#define ASZ (128 * 36)     // A smem stage, stride 36 words (conflict-free)
#define BSZ (32 * 136)     // B smem stage, stride 136 words (conflict-free)
#define STAGES 3
#define GEMM_SMEM (STAGES * (ASZ + BSZ) * 4)

__device__ __forceinline__ void mma_tf32(float* c, const uint32_t* a, const uint32_t* b) {
    asm volatile(
        "mma.sync.aligned.m16n8k8.row.col.f32.tf32.tf32.f32 "
        "{%0,%1,%2,%3}, {%4,%5,%6,%7}, {%8,%9}, {%0,%1,%2,%3};\n"
        : "+f"(c[0]), "+f"(c[1]), "+f"(c[2]), "+f"(c[3])
        : "r"(a[0]), "r"(a[1]), "r"(a[2]), "r"(a[3]), "r"(b[0]), "r"(b[1]));
}

__global__ __launch_bounds__(256)
void gemm_tf32_kernel(const float* __restrict__ A, const float* __restrict__ B,
                      const float* __restrict__ bias, float* __restrict__ C,
                      int M, int N, int K, int epi) {
    extern __shared__ uint32_t smu[];
    uint32_t* As = smu;                     // [STAGES][ASZ]
    uint32_t* Bs = smu + STAGES * ASZ;      // [STAGES][BSZ]

    int tid  = threadIdx.x;
    int wid  = tid >> 5, lane = tid & 31;
    int g    = lane >> 2, t = lane & 3;
    int wm   = wid & 3;              // warp row (0..3) -> m offset wm*32
    int wn   = wid >> 2;             // warp col (0..1) -> n offset wn*64
    int m0   = blockIdx.y * 128, n0 = blockIdx.x * 128;

    float acc[2][8][4];
    #pragma unroll
    for (int i = 0; i < 2; i++)
        #pragma unroll
        for (int j = 0; j < 8; j++)
            #pragma unroll
            for (int r = 0; r < 4; r++) acc[i][j][r] = 0.0f;

    int nk = K >> 5;   // K/32 tiles

    // Pre-computed loader indices
    int a_r = tid >> 3, a_c4 = (tid & 7) * 4;     // + q*32 rows
    int b_r = tid >> 5, b_c4 = (tid & 31) * 4;    // + q*8 rows

    #define ISSUE_STAGE(kt)                                                      \
    do {                                                                         \
        int _kb = (kt) << 5;                                                     \
        uint32_t* _Aw = As + ((kt) % STAGES) * ASZ;                              \
        uint32_t* _Bw = Bs + ((kt) % STAGES) * BSZ;                              \
        _Pragma("unroll")                                                        \
        for (int q = 0; q < 4; q++) {                                            \
            int r = a_r + q * 32;                                                \
            cp16(&_Aw[r * 36 + a_c4], &A[(size_t)(m0 + r) * K + _kb + a_c4]);    \
        }                                                                        \
        _Pragma("unroll")                                                        \
        for (int q = 0; q < 4; q++) {                                            \
            int r = b_r + q * 8;                                                 \
            cp16(&_Bw[r * 136 + b_c4], &B[(size_t)(_kb + r) * N + n0 + b_c4]);   \
        }                                                                        \
        asm volatile("cp.async.commit_group;\n");                                \
    } while (0)

    ISSUE_STAGE(0);
    ISSUE_STAGE(1);

    for (int kt = 0; kt < nk; kt++) {
        asm volatile("cp.async.wait_group 1;\n");
        __syncthreads();
        if (kt + 2 < nk) ISSUE_STAGE(kt + 2);

        const uint32_t* Ab = As + (kt % STAGES) * ASZ;
        const uint32_t* Bb = Bs + (kt % STAGES) * BSZ;

        #pragma unroll
        for (int ks = 0; ks < 4; ks++) {
            int kk = ks * 8;
            uint32_t a[2][4], b[8][2];
            #pragma unroll
            for (int i = 0; i < 2; i++) {
                int rb = wm * 32 + i * 16 + g;
                a[i][0] = rtf(Ab[rb * 36 + kk + t]);
                a[i][1] = rtf(Ab[(rb + 8) * 36 + kk + t]);
                a[i][2] = rtf(Ab[rb * 36 + kk + t + 4]);
                a[i][3] = rtf(Ab[(rb + 8) * 36 + kk + t + 4]);
            }
            #pragma unroll
            for (int j = 0; j < 8; j++) {
                int cb = wn * 64 + j * 8 + g;
                b[j][0] = rtf(Bb[(kk + t) * 136 + cb]);
                b[j][1] = rtf(Bb[(kk + t + 4) * 136 + cb]);
            }
            #pragma unroll
            for (int i = 0; i < 2; i++)
                #pragma unroll
                for (int j = 0; j < 8; j++)
                    mma_tf32(acc[i][j], a[i], b[j]);
        }
    }

    // ---- epilogue
    bool do_bias = (epi & 1), do_gelu = (epi & 2), do_acc = (epi & 4);
    #pragma unroll
    for (int i = 0; i < 2; i++) {
        int row0 = m0 + wm * 32 + i * 16 + g;
        #pragma unroll
        for (int j = 0; j < 8; j++) {
            int col = n0 + wn * 64 + j * 8 + 2 * t;
            float b0v = 0.0f, b1v = 0.0f;
            if (do_bias) { b0v = bias[col]; b1v = bias[col + 1]; }
            float v00 = acc[i][j][0] + b0v, v01 = acc[i][j][1] + b1v;
            float v10 = acc[i][j][2] + b0v, v11 = acc[i][j][3] + b1v;
            if (do_gelu) {
                v00 = gelu_tanh(v00); v01 = gelu_tanh(v01);
                v10 = gelu_tanh(v10); v11 = gelu_tanh(v11);
            }
            float* p0 = &C[(size_t)row0 * N + col];
            float* p1 = &C[(size_t)(row0 + 8) * N + col];
            if (do_acc) {
                float2 o0 = *(float2*)p0;
                float2 o1 = *(float2*)p1;
                v00 += o0.x; v01 += o0.y;
                v10 += o1.x; v11 += o1.y;
            }
            *(float2*)p0 = make_float2(v00, v01);
            *(float2*)p1 = make_float2(v10, v11);
        }
    }
}

// ------------------------------------------------------------------
// Rotary (interleaved pairs), k also scaled by DK^-0.5 = 0.125
// ------------------------------------------------------------------
__global__ void rotary_kernel(float* __restrict__ q, float* __restrict__ k,
                              const float* __restrict__ sint,
                              const float* __restrict__ cost) {
    int idx = blockIdx.x * blockDim.x + threadIdx.x;
    if (idx >= BB * SS * HH * 32) return;
    int i  = idx & 31;
    int t  = idx >> 5;
    int h  = t & 15;
    int bs = t >> 4;
    int s  = bs & (SS - 1);
    float sn = sint[s * 32 + i];
    float cs = cost[s * 32 + i];
    size_t base = (size_t)bs * DD + h * 64 + 2 * i;
    float q0 = q[base], q1 = q[base + 1];
    q[base]     = q0 * cs - q1 * sn;
    q[base + 1] = q1 * cs + q0 * sn;
    float k0 = k[base], k1 = k[base + 1];
    k[base]     = (k0 * cs - k1 * sn) * 0.125f;
    k[base + 1] = (k1 * cs + k0 * sn) * 0.125f;
}

// ------------------------------------------------------------------
// Fused retention attention
// ------------------------------------------------------------------
#define ATTN_SHMEM ((64*68*2 + 64*128 + 64*65 + 64 + 64 + 256) * 4)

__global__ __launch_bounds__(256)
void attn_kernel(const float* __restrict__ q, const float* __restrict__ k,
                 const float* __restrict__ v, const float* __restrict__ g,
                 float* __restrict__ outp) {
    extern __shared__ float sh[];
    float* QsT   = sh;
    float* KsT   = QsT + 64 * 68;
    float* Vs    = KsT + 64 * 68;
    float* St    = Vs + 64 * 128;
    float* absum = St + 64 * 65;
    float* crow  = absum + 64;
    float* red   = crow + 64;

    int tid = threadIdx.x;
    int nt = blockIdx.x, h = blockIdx.y, b = blockIdx.z;
    int n0 = nt * 64;
    int tx = tid & 15, ty = tid >> 4;

    double gamma_d = 1.0 - exp2((double)(-5 - h));
    float lg2g = (float)log2(gamma_d);

    #pragma unroll
    for (int qq = 0; qq < 4; qq++) {
        int p = tid + qq * 256;
        int r = p >> 4;
        int kq = (p & 15) * 4;
        float4 t4 = *(const float4*)&q[((size_t)(b * SS + n0 + r)) * DD + h * 64 + kq];
        QsT[(kq + 0) * 68 + r] = t4.x;
        QsT[(kq + 1) * 68 + r] = t4.y;
        QsT[(kq + 2) * 68 + r] = t4.z;
        QsT[(kq + 3) * 68 + r] = t4.w;
    }
    if (tid < 64) {
        absum[tid] = 0.0f;
        int n = n0 + tid;
        double ssum = (1.0 - pow(gamma_d, (double)(n + 1))) / (1.0 - gamma_d);
        crow[tid] = (float)(1.0 / sqrt(ssum));
    }
    float oa[32];
    #pragma unroll
    for (int i = 0; i < 32; i++) oa[i] = 0.0f;
    int ro = tid >> 2, cg = tid & 3;

    for (int mt = 0; mt <= nt; mt++) {
        int m0 = mt * 64;
        __syncthreads();
        #pragma unroll
        for (int qq = 0; qq < 4; qq++) {
            int p = tid + qq * 256;
            int m = p >> 4;
            int kq = (p & 15) * 4;
            float4 t4 = *(const float4*)&k[((size_t)(b * SS + m0 + m)) * DD + h * 64 + kq];
            KsT[(kq + 0) * 68 + m] = t4.x;
            KsT[(kq + 1) * 68 + m] = t4.y;
            KsT[(kq + 2) * 68 + m] = t4.z;
            KsT[(kq + 3) * 68 + m] = t4.w;
        }
        #pragma unroll
        for (int qq = 0; qq < 8; qq++) {
            int p = tid + qq * 256;
            int m = p >> 5;
            int c4 = (p & 31) * 4;
            *(float4*)&Vs[m * 128 + c4] =
                *(const float4*)&v[((size_t)(b * SS + m0 + m)) * (2 * DD) + h * 128 + c4];
        }
        __syncthreads();

        float scv[4][4] = {};
        #pragma unroll 4
        for (int kk = 0; kk < 64; kk++) {
            float4 av = *(const float4*)&QsT[kk * 68 + ty * 4];
            float4 bv = *(const float4*)&KsT[kk * 68 + tx * 4];
            float a[4] = {av.x, av.y, av.z, av.w};
            float bb[4] = {bv.x, bv.y, bv.z, bv.w};
            #pragma unroll
            for (int i = 0; i < 4; i++)
                #pragma unroll
                for (int j = 0; j < 4; j++)
                    scv[i][j] += a[i] * bb[j];
        }
        float aps[4];
        #pragma unroll
        for (int i = 0; i < 4; i++) {
            int r = ty * 4 + i;
            int n = n0 + r;
            float cc = crow[r];
            float part = 0.0f;
            #pragma unroll
            for (int j = 0; j < 4; j++) {
                int m = m0 + tx * 4 + j;
                float t = 0.0f;
                if (m <= n) t = scv[i][j] * exp2f((float)(n - m) * lg2g) * cc;
                St[r * 65 + tx * 4 + j] = t;
                part += fabsf(t);
            }
            aps[i] = part;
        }
        #pragma unroll
        for (int i = 0; i < 4; i++) {
            float p4 = aps[i];
            #pragma unroll
            for (int off = 8; off > 0; off >>= 1)
                p4 += __shfl_xor_sync(0xffffffffu, p4, off);
            if (tx == 0) absum[ty * 4 + i] += p4;
        }
        __syncthreads();

        for (int m = 0; m < 64; m++) {
            float sv = St[ro * 65 + m];
            const float* vr = &Vs[m * 128];
            #pragma unroll
            for (int jj = 0; jj < 8; jj++) {
                float4 vv = *(const float4*)&vr[jj * 16 + cg * 4];
                oa[jj * 4 + 0] += sv * vv.x;
                oa[jj * 4 + 1] += sv * vv.y;
                oa[jj * 4 + 2] += sv * vv.z;
                oa[jj * 4 + 3] += sv * vv.w;
            }
        }
    }
    __syncthreads();

    float inv = 1.0f / fmaxf(1.0f, absum[ro]);
    float ssq = 0.0f;
    #pragma unroll
    for (int t = 0; t < 32; t++) { oa[t] *= inv; ssq += oa[t] * oa[t]; }
    red[ro * 4 + cg] = ssq;
    __syncthreads();
    float sum = red[ro * 4 + 0] + red[ro * 4 + 1] + red[ro * 4 + 2] + red[ro * 4 + 3];
    float scale = rsqrtf(sum * (1.0f / 128.0f) + 1e-6f);
    int n = n0 + ro;
    size_t gb = ((size_t)(b * SS + n)) * (2 * DD) + h * 128;
    #pragma unroll
    for (int jj = 0; jj < 8; jj++)
        #pragma unroll
        for (int qi = 0; qi < 4; qi++) {
            int c = jj * 16 + cg * 4 + qi;
            float gv = g[gb + c];
            float sl = gv / (1.0f + expf(-gv));
            outp[gb + c] = sl * (oa[jj * 4 + qi] * scale);
        }
}

// ------------------------------------------------------------------
// Final logits + log_softmax (V=2), one warp per token
// ------------------------------------------------------------------
__global__ void logits_kernel(const float* __restrict__ x,
                              const float* __restrict__ Wout,
                              float* __restrict__ outp) {
    int gt = blockIdx.x * blockDim.x + threadIdx.x;
    int warp = gt >> 5, lane = gt & 31;
    if (warp >= MM) return;
    const float* xr = x + (size_t)warp * DD;
    float a0 = 0.0f, a1 = 0.0f;
    for (int kk = lane; kk < DD; kk += 32) {
        float xv = xr[kk];
        a0 += xv * Wout[kk * 2 + 0];
        a1 += xv * Wout[kk * 2 + 1];
    }
    #pragma unroll
    for (int off = 16; off > 0; off >>= 1) {
        a0 += __shfl_xor_sync(0xffffffffu, a0, off);
        a1 += __shfl_xor_sync(0xffffffffu, a1, off);
    }
    if (lane == 0) {
        float mx = fmaxf(a0, a1);
        float lse = mx + logf(expf(a0 - mx) + expf(a1 - mx));
        outp[warp * 2 + 0] = a0 - lse;
        outp[warp * 2 + 1] = a1 - lse;
    }
}

// ------------------------------------------------------------------
// Orchestration
// ------------------------------------------------------------------
extern "C" void kernel_launch(void* const* d_in, const int* in_sizes, int n_in,
                              void* d_out, int out_size) {
    const int*   tokens = (const int*)  d_in[0];
    const float* emb    = (const float*)d_in[1];
    const float* Wq     = (const float*)d_in[2];
    const float* Wk     = (const float*)d_in[3];
    const float* Wv     = (const float*)d_in[4];
    const float* Wg     = (const float*)d_in[5];
    const float* Wo     = (const float*)d_in[6];
    const float* ln1_s  = (const float*)d_in[7];
    const float* ln1_b  = (const float*)d_in[8];
    const float* ln2_s  = (const float*)d_in[9];
    const float* ln2_b  = (const float*)d_in[10];
    const float* W1     = (const float*)d_in[11];
    const float* b1     = (const float*)d_in[12];
    const float* W2     = (const float*)d_in[13];
    const float* b2     = (const float*)d_in[14];
    const float* lnf_s  = (const float*)d_in[15];
    const float* lnf_b  = (const float*)d_in[16];
    const float* Wout   = (const float*)d_in[17];

    float *h, *x, *q, *k, *v, *g, *ao, *ffn, *sint, *cost;
    cudaGetSymbolAddress((void**)&h,    g_h);
    cudaGetSymbolAddress((void**)&x,    g_x);
    cudaGetSymbolAddress((void**)&q,    g_q);
    cudaGetSymbolAddress((void**)&k,    g_k);
    cudaGetSymbolAddress((void**)&v,    g_v);
    cudaGetSymbolAddress((void**)&g,    g_g);
    cudaGetSymbolAddress((void**)&ao,   g_ao);
    cudaGetSymbolAddress((void**)&ffn,  g_ffn);
    cudaGetSymbolAddress((void**)&sint, g_sin);
    cudaGetSymbolAddress((void**)&cost, g_cos);

    cudaFuncSetAttribute(attn_kernel, cudaFuncAttributeMaxDynamicSharedMemorySize,
                         ATTN_SHMEM);
    cudaFuncSetAttribute(gemm_tf32_kernel, cudaFuncAttributeMaxDynamicSharedMemorySize,
                         GEMM_SMEM);

    sincos_kernel<<<(SS * 32 + 255) / 256, 256>>>(sint, cost);
    embed_kernel<<<(MM * DD + 255) / 256, 256>>>(tokens, emb, h);

    for (int l = 0; l < LL; l++) {
        const float* Wq_l = Wq + (size_t)l * DD * DD;
        const float* Wk_l = Wk + (size_t)l * DD * DD;
        const float* Wv_l = Wv + (size_t)l * DD * 2 * DD;
        const float* Wg_l = Wg + (size_t)l * DD * 2 * DD;
        const float* Wo_l = Wo + (size_t)l * 2 * DD * DD;
        const float* W1_l = W1 + (size_t)l * DD * FFN_;
        const float* W2_l = W2 + (size_t)l * FFN_ * DD;
        const float* b1_l = b1 + (size_t)l * FFN_;
        const float* b2_l = b2 + (size_t)l * DD;

        // --- MSR block ---
        ln_kernel<<<MM, 256>>>(h, ln1_s + l * DD, ln1_b + l * DD, x);
        gemm_tf32_kernel<<<dim3(DD / 128, MM / 128), 256, GEMM_SMEM>>>(
            x, Wq_l, nullptr, q, MM, DD, DD, 0);
        gemm_tf32_kernel<<<dim3(DD / 128, MM / 128), 256, GEMM_SMEM>>>(
            x, Wk_l, nullptr, k, MM, DD, DD, 0);
        gemm_tf32_kernel<<<dim3(2 * DD / 128, MM / 128), 256, GEMM_SMEM>>>(
            x, Wv_l, nullptr, v, MM, 2 * DD, DD, 0);
        gemm_tf32_kernel<<<dim3(2 * DD / 128, MM / 128), 256, GEMM_SMEM>>>(
            x, Wg_l, nullptr, g, MM, 2 * DD, DD, 0);
        rotary_kernel<<<(BB * SS * HH * 32 + 255) / 256, 256>>>(q, k, sint, cost);
        attn_kernel<<<dim3(SS / 64, HH, BB), 256, ATTN_SHMEM>>>(q, k, v, g, ao);
        // h += ao @ Wo   (residual fused into epilogue, epi=4)
        gemm_tf32_kernel<<<dim3(DD / 128, MM / 128), 256, GEMM_SMEM>>>(
            ao, Wo_l, nullptr, h, MM, DD, 2 * DD, 4);

        // --- FFN block ---
        ln_kernel<<<MM, 256>>>(h, ln2_s + l * DD, ln2_b + l * DD, x);
        gemm_tf32_kernel<<<dim3(FFN_ / 128, MM / 128), 256, GEMM_SMEM>>>(
            x, W1_l, b1_l, ffn, MM, FFN_, DD, 3);        // bias + gelu
        // h += gelu(...) @ W2 + b2   (bias + residual, epi=5)
        gemm_tf32_kernel<<<dim3(DD / 128, MM / 128), 256, GEMM_SMEM>>>(
            ffn, W2_l, b2_l, h, MM, DD, FFN_, 5);
    }

    ln_kernel<<<MM, 256>>>(h, lnf_s, lnf_b, x);
    logits_kernel<<<MM * 32 / 256, 256>>>(x, Wout, (float*)d_out);
}

// round 10
// speedup vs baseline: 2.4735x; 1.1482x over previous
#include <cuda_runtime.h>
#include <math.h>
#include <stdint.h>

#define BB   4
#define SS   1024
#define DD   1024
#define HH   16
#define DK_  64
#define DV_  128
#define LL   3
#define FFN_ 4096
#define MM   (BB*SS)   // 4096 tokens

// ------------------------------------------------------------------
// Scratch buffers (static device allocations; no cudaMalloc allowed)
// ------------------------------------------------------------------
__device__ float g_h  [MM*DD];       // residual stream
__device__ float g_x  [MM*DD];       // LN output (tf32-rounded)
__device__ float g_q  [MM*DD];
__device__ float g_k  [MM*DD];
__device__ float g_v  [MM*2*DD];
__device__ float g_g  [MM*2*DD];     // gate pre-activation
__device__ float g_ao [MM*2*DD];     // gated attention output (tf32-rounded)
__device__ float g_ffn[MM*FFN_];     // FFN intermediate (tf32-rounded)
__device__ float g_sin[SS*32];
__device__ float g_cos[SS*32];
// tf32-rounded weight copies
__device__ float g_wq[LL*DD*DD];
__device__ float g_wk[LL*DD*DD];
__device__ float g_wv[LL*DD*2*DD];
__device__ float g_wg[LL*DD*2*DD];
__device__ float g_wo[LL*2*DD*DD];
__device__ float g_w1[LL*DD*FFN_];
__device__ float g_w2[LL*FFN_*DD];

// ------------------------------------------------------------------
// Helpers
// ------------------------------------------------------------------
__device__ __forceinline__ float gelu_tanh(float v) {
    const float c = 0.7978845608028654f;   // sqrt(2/pi)
    return 0.5f * v * (1.0f + tanhf(c * (v + 0.044715f * v * v * v)));
}

// round-to-nearest tf32 on a raw fp32 bit pattern (low 13 bits -> 0)
__device__ __forceinline__ uint32_t rtf(uint32_t bits) {
    uint32_t r;
    asm("cvt.rna.tf32.f32 %0, %1;" : "=r"(r) : "r"(bits));
    return r;
}
__device__ __forceinline__ float rtf_f(float x) {
    return __uint_as_float(rtf(__float_as_uint(x)));
}

__device__ __forceinline__ void cp16(void* smem_dst, const void* gsrc) {
    uint32_t a = (uint32_t)__cvta_generic_to_shared(smem_dst);
    asm volatile("cp.async.cg.shared.global [%0], [%1], 16;\n" :: "r"(a), "l"(gsrc));
}

__device__ __forceinline__ float blockReduceSum(float val, float* sh) {
    #pragma unroll
    for (int off = 16; off > 0; off >>= 1)
        val += __shfl_xor_sync(0xffffffffu, val, off);
    int w = threadIdx.x >> 5, l = threadIdx.x & 31;
    __syncthreads();
    if (l == 0) sh[w] = val;
    __syncthreads();
    float r = (threadIdx.x < (blockDim.x >> 5)) ? sh[threadIdx.x] : 0.0f;
    if (w == 0) {
        #pragma unroll
        for (int off = 16; off > 0; off >>= 1)
            r += __shfl_xor_sync(0xffffffffu, r, off);
        if (l == 0) sh[0] = r;
    }
    __syncthreads();
    return sh[0];
}

// ------------------------------------------------------------------
// tf32 pre-rounding of a buffer (vectorized)
// ------------------------------------------------------------------
__global__ void round_kernel(const uint4* __restrict__ src, uint4* __restrict__ dst, int n4) {
    int i = blockIdx.x * blockDim.x + threadIdx.x;
    if (i < n4) {
        uint4 u = src[i];
        u.x = rtf(u.x); u.y = rtf(u.y); u.z = rtf(u.z); u.w = rtf(u.w);
        dst[i] = u;
    }
}

// ------------------------------------------------------------------
// sin/cos rotary tables (double precision)
// ------------------------------------------------------------------
__global__ void sincos_kernel(float* __restrict__ sint, float* __restrict__ cost) {
    int idx = blockIdx.x * blockDim.x + threadIdx.x;
    if (idx >= SS * 32) return;
    int i = idx & 31;
    int s = idx >> 5;
    double ang = pow(10000.0, -(double)i / 31.0);
    double a = (double)s * ang;
    sint[idx] = (float)sin(a);
    cost[idx] = (float)cos(a);
}

// ------------------------------------------------------------------
// Embedding with right-shift
// ------------------------------------------------------------------
__global__ void embed_kernel(const int* __restrict__ tokens,
                             const float* __restrict__ emb,
                             float* __restrict__ h) {
    int idx = blockIdx.x * blockDim.x + threadIdx.x;
    if (idx >= MM * DD) return;
    int d  = idx & (DD - 1);
    int bs = idx / DD;
    int s  = bs & (SS - 1);
    int b  = bs / SS;
    int tok = (s == 0) ? 0 : tokens[b * SS + s - 1];
    h[idx] = emb[tok * DD + d] * 32.0f;
}

// ------------------------------------------------------------------
// LayerNorm (two-pass, eps 1e-5). Output tf32-rounded (GEMM A input).
// ------------------------------------------------------------------
__global__ __launch_bounds__(256)
void ln_kernel(const float* __restrict__ x, const float* __restrict__ sc,
               const float* __restrict__ bi, float* __restrict__ y) {
    __shared__ float sh[32];
    int row = blockIdx.x;
    int tid = threadIdx.x;
    const float* xr = x + (size_t)row * DD;
    float v[4];
    float sum = 0.0f;
    #pragma unroll
    for (int j = 0; j < 4; j++) { v[j] = xr[tid + j * 256]; sum += v[j]; }
    sum = blockReduceSum(sum, sh);
    float mean = sum * (1.0f / 1024.0f);
    float vs = 0.0f;
    #pragma unroll
    for (int j = 0; j < 4; j++) { float d = v[j] - mean; vs += d * d; }
    vs = blockReduceSum(vs, sh);
    float invstd = rsqrtf(vs * (1.0f / 1024.0f) + 1e-5f);
    float* yr = y + (size_t)row * DD;
    #pragma unroll
    for (int j = 0; j < 4; j++) {
        int c = tid + j * 256;
        yr[c] = rtf_f((v[j] - mean) * invstd * sc[c] + bi[c]);
    }
}

// ------------------------------------------------------------------
// TF32 tensor-core GEMM: C[M,N] = A[M,K] @ B[K,N]
// A and B must be tf32-pre-rounded fp32 (HW truncation is then lossless).
// Block tile 128x128, BK=32, 256 threads, warp tile 32x64.
// cp.async double-buffered. No cvt in the mainloop.
// epi bitmask: 1 = +bias, 2 = gelu (output tf32-rounded), 4 = C += result
// ------------------------------------------------------------------
#define ASZ (128 * 36)     // A smem stage, stride 36 words (conflict-free)
#define BSZ (32 * 136)     // B smem stage, stride 136 words (conflict-free)
#define STAGES 2
#define GEMM_SMEM (STAGES * (ASZ + BSZ) * 4)

__device__ __forceinline__ void mma_tf32(float* c, const uint32_t* a, const uint32_t* b) {
    asm volatile(
        "mma.sync.aligned.m16n8k8.row.col.f32.tf32.tf32.f32 "
        "{%0,%1,%2,%3}, {%4,%5,%6,%7}, {%8,%9}, {%0,%1,%2,%3};\n"
        : "+f"(c[0]), "+f"(c[1]), "+f"(c[2]), "+f"(c[3])
        : "r"(a[0]), "r"(a[1]), "r"(a[2]), "r"(a[3]), "r"(b[0]), "r"(b[1]));
}

__global__ __launch_bounds__(256, 2)
void gemm_tf32_kernel(const float* __restrict__ A, const float* __restrict__ B,
                      const float* __restrict__ bias, float* __restrict__ C,
                      int M, int N, int K, int epi) {
    extern __shared__ uint32_t smu[];
    uint32_t* As = smu;                     // [STAGES][ASZ]
    uint32_t* Bs = smu + STAGES * ASZ;      // [STAGES][BSZ]

    int tid  = threadIdx.x;
    int wid  = tid >> 5, lane = tid & 31;
    int g    = lane >> 2, t = lane & 3;
    int wm   = wid & 3;              // warp row (0..3) -> m offset wm*32
    int wn   = wid >> 2;             // warp col (0..1) -> n offset wn*64
    int m0   = blockIdx.y * 128, n0 = blockIdx.x * 128;

    float acc[2][8][4];
    #pragma unroll
    for (int i = 0; i < 2; i++)
        #pragma unroll
        for (int j = 0; j < 8; j++)
            #pragma unroll
            for (int r = 0; r < 4; r++) acc[i][j][r] = 0.0f;

    int nk = K >> 5;   // K/32 tiles

    // Pre-computed loader indices
    int a_r = tid >> 3, a_c4 = (tid & 7) * 4;     // + q*32 rows
    int b_r = tid >> 5, b_c4 = (tid & 31) * 4;    // + q*8 rows

    #define ISSUE_STAGE(kt)                                                      \
    do {                                                                         \
        int _kb = (kt) << 5;                                                     \
        uint32_t* _Aw = As + ((kt) & 1) * ASZ;                                   \
        uint32_t* _Bw = Bs + ((kt) & 1) * BSZ;                                   \
        _Pragma("unroll")                                                        \
        for (int q = 0; q < 4; q++) {                                            \
            int r = a_r + q * 32;                                                \
            cp16(&_Aw[r * 36 + a_c4], &A[(size_t)(m0 + r) * K + _kb + a_c4]);    \
        }                                                                        \
        _Pragma("unroll")                                                        \
        for (int q = 0; q < 4; q++) {                                            \
            int r = b_r + q * 8;                                                 \
            cp16(&_Bw[r * 136 + b_c4], &B[(size_t)(_kb + r) * N + n0 + b_c4]);   \
        }                                                                        \
        asm volatile("cp.async.commit_group;\n");                                \
    } while (0)

    ISSUE_STAGE(0);
    ISSUE_STAGE(1);

    for (int kt = 0; kt < nk; kt++) {
        asm volatile("cp.async.wait_group 1;\n");
        __syncthreads();

        const uint32_t* Ab = As + (kt & 1) * ASZ;
        const uint32_t* Bb = Bs + (kt & 1) * BSZ;

        #pragma unroll
        for (int ks = 0; ks < 4; ks++) {
            int kk = ks * 8;
            uint32_t a[2][4], b[8][2];
            #pragma unroll
            for (int i = 0; i < 2; i++) {
                int rb = wm * 32 + i * 16 + g;
                a[i][0] = Ab[rb * 36 + kk + t];
                a[i][1] = Ab[(rb + 8) * 36 + kk + t];
                a[i][2] = Ab[rb * 36 + kk + t + 4];
                a[i][3] = Ab[(rb + 8) * 36 + kk + t + 4];
            }
            #pragma unroll
            for (int j = 0; j < 8; j++) {
                int cb = wn * 64 + j * 8 + g;
                b[j][0] = Bb[(kk + t) * 136 + cb];
                b[j][1] = Bb[(kk + t + 4) * 136 + cb];
            }
            #pragma unroll
            for (int i = 0; i < 2; i++)
                #pragma unroll
                for (int j = 0; j < 8; j++)
                    mma_tf32(acc[i][j], a[i], b[j]);
        }

        __syncthreads();   // all warps done reading this buffer
        if (kt + 2 < nk) ISSUE_STAGE(kt + 2);
    }

    // ---- epilogue
    bool do_bias = (epi & 1), do_gelu = (epi & 2), do_acc = (epi & 4);
    #pragma unroll
    for (int i = 0; i < 2; i++) {
        int row0 = m0 + wm * 32 + i * 16 + g;
        #pragma unroll
        for (int j = 0; j < 8; j++) {
            int col = n0 + wn * 64 + j * 8 + 2 * t;
            float b0v = 0.0f, b1v = 0.0f;
            if (do_bias) { b0v = bias[col]; b1v = bias[col + 1]; }
            float v00 = acc[i][j][0] + b0v, v01 = acc[i][j][1] + b1v;
            float v10 = acc[i][j][2] + b0v, v11 = acc[i][j][3] + b1v;
            if (do_gelu) {
                v00 = rtf_f(gelu_tanh(v00)); v01 = rtf_f(gelu_tanh(v01));
                v10 = rtf_f(gelu_tanh(v10)); v11 = rtf_f(gelu_tanh(v11));
            }
            float* p0 = &C[(size_t)row0 * N + col];
            float* p1 = &C[(size_t)(row0 + 8) * N + col];
            if (do_acc) {
                float2 o0 = *(float2*)p0;
                float2 o1 = *(float2*)p1;
                v00 += o0.x; v01 += o0.y;
                v10 += o1.x; v11 += o1.y;
            }
            *(float2*)p0 = make_float2(v00, v01);
            *(float2*)p1 = make_float2(v10, v11);
        }
    }
}

// ------------------------------------------------------------------
// Rotary (interleaved pairs), k also scaled by DK^-0.5 = 0.125
// ------------------------------------------------------------------
__global__ void rotary_kernel(float* __restrict__ q, float* __restrict__ k,
                              const float* __restrict__ sint,
                              const float* __restrict__ cost) {
    int idx = blockIdx.x * blockDim.x + threadIdx.x;
    if (idx >= BB * SS * HH * 32) return;
    int i  = idx & 31;
    int t  = idx >> 5;
    int h  = t & 15;
    int bs = t >> 4;
    int s  = bs & (SS - 1);
    float sn = sint[s * 32 + i];
    float cs = cost[s * 32 + i];
    size_t base = (size_t)bs * DD + h * 64 + 2 * i;
    float q0 = q[base], q1 = q[base + 1];
    q[base]     = q0 * cs - q1 * sn;
    q[base + 1] = q1 * cs + q0 * sn;
    float k0 = k[base], k1 = k[base + 1];
    k[base]     = (k0 * cs - k1 * sn) * 0.125f;
    k[base + 1] = (k1 * cs + k0 * sn) * 0.125f;
}

// ------------------------------------------------------------------
// Fused retention attention. Output tf32-rounded (Wo GEMM A input).
// ------------------------------------------------------------------
#define ATTN_SHMEM ((64*68*2 + 64*128 + 64*65 + 64 + 64 + 256) * 4)

__global__ __launch_bounds__(256)
void attn_kernel(const float* __restrict__ q, const float* __restrict__ k,
                 const float* __restrict__ v, const float* __restrict__ g,
                 float* __restrict__ outp) {
    extern __shared__ float sh[];
    float* QsT   = sh;
    float* KsT   = QsT + 64 * 68;
    float* Vs    = KsT + 64 * 68;
    float* St    = Vs + 64 * 128;
    float* absum = St + 64 * 65;
    float* crow  = absum + 64;
    float* red   = crow + 64;

    int tid = threadIdx.x;
    int nt = blockIdx.x, h = blockIdx.y, b = blockIdx.z;
    int n0 = nt * 64;
    int tx = tid & 15, ty = tid >> 4;

    double gamma_d = 1.0 - exp2((double)(-5 - h));
    float lg2g = (float)log2(gamma_d);

    #pragma unroll
    for (int qq = 0; qq < 4; qq++) {
        int p = tid + qq * 256;
        int r = p >> 4;
        int kq = (p & 15) * 4;
        float4 t4 = *(const float4*)&q[((size_t)(b * SS + n0 + r)) * DD + h * 64 + kq];
        QsT[(kq + 0) * 68 + r] = t4.x;
        QsT[(kq + 1) * 68 + r] = t4.y;
        QsT[(kq + 2) * 68 + r] = t4.z;
        QsT[(kq + 3) * 68 + r] = t4.w;
    }
    if (tid < 64) {
        absum[tid] = 0.0f;
        int n = n0 + tid;
        double ssum = (1.0 - pow(gamma_d, (double)(n + 1))) / (1.0 - gamma_d);
        crow[tid] = (float)(1.0 / sqrt(ssum));
    }
    float oa[32];
    #pragma unroll
    for (int i = 0; i < 32; i++) oa[i] = 0.0f;
    int ro = tid >> 2, cg = tid & 3;

    for (int mt = 0; mt <= nt; mt++) {
        int m0 = mt * 64;
        __syncthreads();
        #pragma unroll
        for (int qq = 0; qq < 4; qq++) {
            int p = tid + qq * 256;
            int m = p >> 4;
            int kq = (p & 15) * 4;
            float4 t4 = *(const float4*)&k[((size_t)(b * SS + m0 + m)) * DD + h * 64 + kq];
            KsT[(kq + 0) * 68 + m] = t4.x;
            KsT[(kq + 1) * 68 + m] = t4.y;
            KsT[(kq + 2) * 68 + m] = t4.z;
            KsT[(kq + 3) * 68 + m] = t4.w;
        }
        #pragma unroll
        for (int qq = 0; qq < 8; qq++) {
            int p = tid + qq * 256;
            int m = p >> 5;
            int c4 = (p & 31) * 4;
            *(float4*)&Vs[m * 128 + c4] =
                *(const float4*)&v[((size_t)(b * SS + m0 + m)) * (2 * DD) + h * 128 + c4];
        }
        __syncthreads();

        float scv[4][4] = {};
        #pragma unroll 4
        for (int kk = 0; kk < 64; kk++) {
            float4 av = *(const float4*)&QsT[kk * 68 + ty * 4];
            float4 bv = *(const float4*)&KsT[kk * 68 + tx * 4];
            float a[4] = {av.x, av.y, av.z, av.w};
            float bb[4] = {bv.x, bv.y, bv.z, bv.w};
            #pragma unroll
            for (int i = 0; i < 4; i++)
                #pragma unroll
                for (int j = 0; j < 4; j++)
                    scv[i][j] += a[i] * bb[j];
        }
        float aps[4];
        #pragma unroll
        for (int i = 0; i < 4; i++) {
            int r = ty * 4 + i;
            int n = n0 + r;
            float cc = crow[r];
            float part = 0.0f;
            #pragma unroll
            for (int j = 0; j < 4; j++) {
                int m = m0 + tx * 4 + j;
                float t = 0.0f;
                if (m <= n) t = scv[i][j] * exp2f((float)(n - m) * lg2g) * cc;
                St[r * 65 + tx * 4 + j] = t;
                part += fabsf(t);
            }
            aps[i] = part;
        }
        #pragma unroll
        for (int i = 0; i < 4; i++) {
            float p4 = aps[i];
            #pragma unroll
            for (int off = 8; off > 0; off >>= 1)
                p4 += __shfl_xor_sync(0xffffffffu, p4, off);
            if (tx == 0) absum[ty * 4 + i] += p4;
        }
        __syncthreads();

        for (int m = 0; m < 64; m++) {
            float sv = St[ro * 65 + m];
            const float* vr = &Vs[m * 128];
            #pragma unroll
            for (int jj = 0; jj < 8; jj++) {
                float4 vv = *(const float4*)&vr[jj * 16 + cg * 4];
                oa[jj * 4 + 0] += sv * vv.x;
                oa[jj * 4 + 1] += sv * vv.y;
                oa[jj * 4 + 2] += sv * vv.z;
                oa[jj * 4 + 3] += sv * vv.w;
            }
        }
    }
    __syncthreads();

    float inv = 1.0f / fmaxf(1.0f, absum[ro]);
    float ssq = 0.0f;
    #pragma unroll
    for (int t = 0; t < 32; t++) { oa[t] *= inv; ssq += oa[t] * oa[t]; }
    red[ro * 4 + cg] = ssq;
    __syncthreads();
    float sum = red[ro * 4 + 0] + red[ro * 4 + 1] + red[ro * 4 + 2] + red[ro * 4 + 3];
    float scale = rsqrtf(sum * (1.0f / 128.0f) + 1e-6f);
    int n = n0 + ro;
    size_t gb = ((size_t)(b * SS + n)) * (2 * DD) + h * 128;
    #pragma unroll
    for (int jj = 0; jj < 8; jj++)
        #pragma unroll
        for (int qi = 0; qi < 4; qi++) {
            int c = jj * 16 + cg * 4 + qi;
            float gv = g[gb + c];
            float sl = gv / (1.0f + expf(-gv));
            outp[gb + c] = rtf_f(sl * (oa[jj * 4 + qi] * scale));
        }
}

// ------------------------------------------------------------------
// Final logits + log_softmax (V=2), one warp per token
// ------------------------------------------------------------------
__global__ void logits_kernel(const float* __restrict__ x,
                              const float* __restrict__ Wout,
                              float* __restrict__ outp) {
    int gt = blockIdx.x * blockDim.x + threadIdx.x;
    int warp = gt >> 5, lane = gt & 31;
    if (warp >= MM) return;
    const float* xr = x + (size_t)warp * DD;
    float a0 = 0.0f, a1 = 0.0f;
    for (int kk = lane; kk < DD; kk += 32) {
        float xv = xr[kk];
        a0 += xv * Wout[kk * 2 + 0];
        a1 += xv * Wout[kk * 2 + 1];
    }
    #pragma unroll
    for (int off = 16; off > 0; off >>= 1) {
        a0 += __shfl_xor_sync(0xffffffffu, a0, off);
        a1 += __shfl_xor_sync(0xffffffffu, a1, off);
    }
    if (lane == 0) {
        float mx = fmaxf(a0, a1);
        float lse = mx + logf(expf(a0 - mx) + expf(a1 - mx));
        outp[warp * 2 + 0] = a0 - lse;
        outp[warp * 2 + 1] = a1 - lse;
    }
}

// ------------------------------------------------------------------
// Orchestration
// ------------------------------------------------------------------
extern "C" void kernel_launch(void* const* d_in, const int* in_sizes, int n_in,
                              void* d_out, int out_size) {
    const int*   tokens = (const int*)  d_in[0];
    const float* emb    = (const float*)d_in[1];
    const float* Wq     = (const float*)d_in[2];
    const float* Wk     = (const float*)d_in[3];
    const float* Wv     = (const float*)d_in[4];
    const float* Wg     = (const float*)d_in[5];
    const float* Wo     = (const float*)d_in[6];
    const float* ln1_s  = (const float*)d_in[7];
    const float* ln1_b  = (const float*)d_in[8];
    const float* ln2_s  = (const float*)d_in[9];
    const float* ln2_b  = (const float*)d_in[10];
    const float* W1     = (const float*)d_in[11];
    const float* b1     = (const float*)d_in[12];
    const float* W2     = (const float*)d_in[13];
    const float* b2     = (const float*)d_in[14];
    const float* lnf_s  = (const float*)d_in[15];
    const float* lnf_b  = (const float*)d_in[16];
    const float* Wout   = (const float*)d_in[17];

    float *h, *x, *q, *k, *v, *g, *ao, *ffn, *sint, *cost;
    float *wq, *wk, *wv, *wg, *wo, *w1, *w2;
    cudaGetSymbolAddress((void**)&h,    g_h);
    cudaGetSymbolAddress((void**)&x,    g_x);
    cudaGetSymbolAddress((void**)&q,    g_q);
    cudaGetSymbolAddress((void**)&k,    g_k);
    cudaGetSymbolAddress((void**)&v,    g_v);
    cudaGetSymbolAddress((void**)&g,    g_g);
    cudaGetSymbolAddress((void**)&ao,   g_ao);
    cudaGetSymbolAddress((void**)&ffn,  g_ffn);
    cudaGetSymbolAddress((void**)&sint, g_sin);
    cudaGetSymbolAddress((void**)&cost, g_cos);
    cudaGetSymbolAddress((void**)&wq,   g_wq);
    cudaGetSymbolAddress((void**)&wk,   g_wk);
    cudaGetSymbolAddress((void**)&wv,   g_wv);
    cudaGetSymbolAddress((void**)&wg,   g_wg);
    cudaGetSymbolAddress((void**)&wo,   g_wo);
    cudaGetSymbolAddress((void**)&w1,   g_w1);
    cudaGetSymbolAddress((void**)&w2,   g_w2);

    cudaFuncSetAttribute(attn_kernel, cudaFuncAttributeMaxDynamicSharedMemorySize,
                         ATTN_SHMEM);
    cudaFuncSetAttribute(gemm_tf32_kernel, cudaFuncAttributeMaxDynamicSharedMemorySize,
                         GEMM_SMEM);

    sincos_kernel<<<(SS * 32 + 255) / 256, 256>>>(sint, cost);
    embed_kernel<<<(MM * DD + 255) / 256, 256>>>(tokens, emb, h);

    // Pre-round all weights to tf32 values (once per launch)
    #define ROUND(src, dst, n)                                                   \
        round_kernel<<<((n) / 4 + 255) / 256, 256>>>(                            \
            (const uint4*)(src), (uint4*)(dst), (n) / 4)
    ROUND(Wq, wq, LL * DD * DD);
    ROUND(Wk, wk, LL * DD * DD);
    ROUND(Wv, wv, LL * DD * 2 * DD);
    ROUND(Wg, wg, LL * DD * 2 * DD);
    ROUND(Wo, wo, LL * 2 * DD * DD);
    ROUND(W1, w1, LL * DD * FFN_);
    ROUND(W2, w2, LL * FFN_ * DD);

    for (int l = 0; l < LL; l++) {
        const float* Wq_l = wq + (size_t)l * DD * DD;
        const float* Wk_l = wk + (size_t)l * DD * DD;
        const float* Wv_l = wv + (size_t)l * DD * 2 * DD;
        const float* Wg_l = wg + (size_t)l * DD * 2 * DD;
        const float* Wo_l = wo + (size_t)l * 2 * DD * DD;
        const float* W1_l = w1 + (size_t)l * DD * FFN_;
        const float* W2_l = w2 + (size_t)l * FFN_ * DD;
        const float* b1_l = b1 + (size_t)l * FFN_;
        const float* b2_l = b2 + (size_t)l * DD;

        // --- MSR block ---
        ln_kernel<<<MM, 256>>>(h, ln1_s + l * DD, ln1_b + l * DD, x);
        gemm_tf32_kernel<<<dim3(DD / 128, MM / 128), 256, GEMM_SMEM>>>(
            x, Wq_l, nullptr, q, MM, DD, DD, 0);
        gemm_tf32_kernel<<<dim3(DD / 128, MM / 128), 256, GEMM_SMEM>>>(
            x, Wk_l, nullptr, k, MM, DD, DD, 0);
        gemm_tf32_kernel<<<dim3(2 * DD / 128, MM / 128), 256, GEMM_SMEM>>>(
            x, Wv_l, nullptr, v, MM, 2 * DD, DD, 0);
        gemm_tf32_kernel<<<dim3(2 * DD / 128, MM / 128), 256, GEMM_SMEM>>>(
            x, Wg_l, nullptr, g, MM, 2 * DD, DD, 0);
        rotary_kernel<<<(BB * SS * HH * 32 + 255) / 256, 256>>>(q, k, sint, cost);
        attn_kernel<<<dim3(SS / 64, HH, BB), 256, ATTN_SHMEM>>>(q, k, v, g, ao);
        // h += ao @ Wo   (residual fused into epilogue, epi=4)
        gemm_tf32_kernel<<<dim3(DD / 128, MM / 128), 256, GEMM_SMEM>>>(
            ao, Wo_l, nullptr, h, MM, DD, 2 * DD, 4);

        // --- FFN block ---
        ln_kernel<<<MM, 256>>>(h, ln2_s + l * DD, ln2_b + l * DD, x);
        gemm_tf32_kernel<<<dim3(FFN_ / 128, MM / 128), 256, GEMM_SMEM>>>(
            x, W1_l, b1_l, ffn, MM, FFN_, DD, 3);        // bias + gelu (rounded)
        // h += gelu(...) @ W2 + b2   (bias + residual, epi=5)
        gemm_tf32_kernel<<<dim3(DD / 128, MM / 128), 256, GEMM_SMEM>>>(
            ffn, W2_l, b2_l, h, MM, DD, FFN_, 5);
    }

    ln_kernel<<<MM, 256>>>(h, lnf_s, lnf_b, x);
    logits_kernel<<<MM * 32 / 256, 256>>>(x, Wout, (float*)d_out);
}